// round 11
// baseline (speedup 1.0000x reference)
#include <cuda_runtime.h>
#include <cuda_fp16.h>
#include <cstdint>

// Problem dims (fixed)
#define NB   8
#define LQ   1024
#define SSEQ 4096
#define DD   512

#ifndef __CUDA_ARCH_SPECIFIC__
#define __CUDA_ARCH_SPECIFIC__ 0
#endif
#if defined(__CUDA_ARCH_FEAT_SM103_ALL) || defined(__CUDA_ARCH_FEAT_SM100_ALL) || (__CUDA_ARCH_SPECIFIC__ >= 1000)
#define HAS_TCGEN05 1
#else
#define HAS_TCGEN05 0
#endif

// ---------------- static device scratch (no allocations allowed) ----------------
static __device__ __half g_q  [NB * LQ * DD];
static __device__ __half g_k  [NB * SSEQ * DD];
static __device__ __half g_vT [NB * DD * SSEQ];
static __device__ __half g_s  [NB * LQ * SSEQ];       // exp(dist-12), unnormalized
static __device__ __half g_msg[NB * LQ * DD];
static __device__ __half g_mln[NB * LQ * DD];
static __device__ __half g_hid[NB * LQ * 2 * DD];
static __device__ __half g_xr [NB * LQ * DD];
static __device__ __half g_srcr[NB * SSEQ * DD];
static __device__ __half g_wth[4 * DD * DD + 4 * DD * DD + 2 * DD * DD];
static __device__ float g_q2 [NB * LQ];
static __device__ float g_k2 [NB * SSEQ];
static __device__ float g_ssum[NB * LQ];
static __device__ float g_mw [NB * LQ * DD];
static __device__ float g_ffn[NB * LQ * DD];

// ======================= PTX helpers =======================
__device__ __forceinline__ uint32_t smem_u32(const void* p) {
    uint32_t a;
    asm("{ .reg .u64 t; cvta.to.shared.u64 t, %1; cvt.u32.u64 %0, t; }" : "=r"(a) : "l"(p));
    return a;
}
#define CP_ASYNC16(dst, src) \
    asm volatile("cp.async.cg.shared.global [%0], [%1], 16;" :: "r"(dst), "l"(src) : "memory")

#if HAS_TCGEN05
__device__ __forceinline__ uint32_t elect_one() {
    uint32_t pred;
    asm volatile("{\n\t.reg .pred p;\n\telect.sync _|p, 0xFFFFFFFF;\n\t"
                 "selp.b32 %0, 1, 0, p;\n\t}" : "=r"(pred));
    return pred;
}
#define MBAR_INIT(addr, cnt) \
    asm volatile("mbarrier.init.shared.b64 [%0], %1;" :: "r"(addr), "r"(cnt) : "memory")
#define MBAR_INVAL(addr) \
    asm volatile("mbarrier.inval.shared.b64 [%0];" :: "r"(addr) : "memory")
#define CP_MBAR_ARRIVE(addr) \
    asm volatile("cp.async.mbarrier.arrive.noinc.shared.b64 [%0];" :: "r"(addr) : "memory")
__device__ __forceinline__ void mbar_wait(uint32_t addr, uint32_t parity) {
    uint32_t done;
    asm volatile("{\n\t.reg .pred p;\n\t"
                 "mbarrier.try_wait.parity.acquire.cta.shared::cta.b64 p, [%1], %2;\n\t"
                 "selp.b32 %0, 1, 0, p;\n\t}" : "=r"(done) : "r"(addr), "r"(parity) : "memory");
    if (!done) {
        asm volatile("{\n\t.reg .pred P1;\n\t"
                     "W_%=:\n\t"
                     "mbarrier.try_wait.parity.acquire.cta.shared::cta.b64 P1, [%0], %1, 0x989680;\n\t"
                     "@P1 bra.uni D_%=;\n\t"
                     "bra.uni W_%=;\n\t"
                     "D_%=:\n\t}" :: "r"(addr), "r"(parity) : "memory");
    }
}
#define TC_ALLOC(smem_addr, n) \
    asm volatile("tcgen05.alloc.cta_group::1.sync.aligned.shared::cta.b32 [%0], %1;" \
                 :: "r"(smem_addr), "r"(n) : "memory")
#define TC_DEALLOC(tmem, n) \
    asm volatile("tcgen05.dealloc.cta_group::1.sync.aligned.b32 %0, %1;" :: "r"(tmem), "r"(n))
#define TC_RELINQ() \
    asm volatile("tcgen05.relinquish_alloc_permit.cta_group::1.sync.aligned;")
#define TC_COMMIT(mbar) \
    asm volatile("tcgen05.commit.cta_group::1.mbarrier::arrive::one.shared::cluster.b64 [%0];" \
                 :: "r"(mbar) : "memory")
#define TC_FENCE_AFTER() asm volatile("tcgen05.fence::after_thread_sync;" ::: "memory")
#define TC_WAIT_LD()     asm volatile("tcgen05.wait::ld.sync.aligned;" ::: "memory")
#define FENCE_ASYNC()    asm volatile("fence.proxy.async.shared::cta;" ::: "memory")

__device__ __forceinline__ void mma_f16_ss(uint32_t d, uint64_t a, uint64_t b,
                                           uint32_t idesc, uint32_t en) {
    asm volatile("{\n\t.reg .pred p;\n\tsetp.ne.u32 p, %4, 0;\n\t"
                 "tcgen05.mma.cta_group::1.kind::f16 [%0], %1, %2, %3, {%5,%5,%5,%5}, p;\n\t}"
                 :: "r"(d), "l"(a), "l"(b), "r"(idesc), "r"(en), "r"(0u) : "memory");
}
__device__ __forceinline__ void tmem_ld_x32(uint32_t* r, uint32_t addr) {
    asm volatile(
        "tcgen05.ld.sync.aligned.32x32b.x32.b32 "
        "{%0,%1,%2,%3,%4,%5,%6,%7,%8,%9,%10,%11,%12,%13,%14,%15,"
        "%16,%17,%18,%19,%20,%21,%22,%23,%24,%25,%26,%27,%28,%29,%30,%31}, [%32];"
        : "=r"(r[0]), "=r"(r[1]), "=r"(r[2]), "=r"(r[3]), "=r"(r[4]), "=r"(r[5]),
          "=r"(r[6]), "=r"(r[7]), "=r"(r[8]), "=r"(r[9]), "=r"(r[10]), "=r"(r[11]),
          "=r"(r[12]), "=r"(r[13]), "=r"(r[14]), "=r"(r[15]), "=r"(r[16]), "=r"(r[17]),
          "=r"(r[18]), "=r"(r[19]), "=r"(r[20]), "=r"(r[21]), "=r"(r[22]), "=r"(r[23]),
          "=r"(r[24]), "=r"(r[25]), "=r"(r[26]), "=r"(r[27]), "=r"(r[28]), "=r"(r[29]),
          "=r"(r[30]), "=r"(r[31])
        : "r"(addr));
}
__device__ __forceinline__ uint32_t sw128(uint32_t b) { return b ^ ((b >> 3) & 0x70); }
static __device__ __forceinline__ uint64_t make_desc(uint32_t addr) {
    const uint64_t base = (uint64_t(2) << 61) | (uint64_t(1) << 46)
                        | (uint64_t(64) << 32) | (uint64_t(1) << 16);
    return base | ((uint64_t)(addr >> 4) & 0x3FFF);
}
#define IDESC_F16 ((1u << 4) | ((128u / 8u) << 17) | ((128u / 16u) << 24))
#endif  // HAS_TCGEN05

// ======================================================================
// NT GEMM: C[M,N] = A[M,K] * Bt[N,K]^T; fp16 operands, fp32 accumulate.
// CTA tile 128(M) x 256(N), K chunks of 64. 2-slot ring (48KB/slot), 2 CTAs/SM.
// Warp-specialized mainloop (NO __syncthreads in loop):
//   all 256 threads: [wait slot free] -> 12x cp.async -> cp.async.mbarrier.arrive
//   warp 0 elected:  wait slot full(256 arrivals) -> fence -> 8 MMAs -> commit(free)
// EPI: 0 none, 1 exp(dist-12)+row-sum, 2 relu, 3 div-by-rn, 4 fp16+sumsq(rownorm)
// OUTH: 1 fp16 out, 0 fp32 out.  DUAL: A = [gA | gA2] along K.
// ======================================================================
template<int EPI, int DUAL, int OUTH>
__global__ __launch_bounds__(256)
void tc_gemm(const __half* __restrict__ gA, const __half* __restrict__ gA2,
             const __half* __restrict__ gB, void* __restrict__ gC,
             int N, int K, int lda, int ldb,
             long long sA, long long sB, long long sC,
             const float* __restrict__ rn, const float* __restrict__ cn,
             float* __restrict__ sum)
{
    extern __shared__ __align__(1024) char dyn_smem[];

    const int tid = threadIdx.x;
    const int wid = tid >> 5, lane = tid & 31;

    const long long z = blockIdx.z;
    const __half* Abase  = gA + z * sA + (long long)blockIdx.y * 128 * lda;
    const __half* A2base = DUAL ? (gA2 + (long long)blockIdx.y * 128 * lda) : nullptr;
    const __half* Bbase  = gB + z * sB + (long long)blockIdx.x * 256 * ldb;
    const long long Coff = z * sC + (long long)blockIdx.y * 128 * N + blockIdx.x * 256;
    const int Mtot = gridDim.y * 128;

#if HAS_TCGEN05
    __shared__ uint32_t s_tmem[1];
    __shared__ __align__(8) uint64_t s_mbar[4];   // full0, full1, free0, free1

    const uint32_t smem_base = smem_u32(dyn_smem);
    const uint32_t mb = smem_u32(&s_mbar[0]);
    const uint32_t full0 = mb, full1 = mb + 8, free0 = mb + 16, free1 = mb + 24;

    if (wid == 0) {
        TC_ALLOC(smem_u32(s_tmem), 256);
        TC_RELINQ();
    }
    if (tid == 0) {
        MBAR_INIT(full0, 256); MBAR_INIT(full1, 256);
        MBAR_INIT(free0, 1);   MBAR_INIT(free1, 1);
    }
    __syncthreads();
    const uint32_t tmem = s_tmem[0];

    // loader geometry: rows of 64 halfs = 128B, SW128; 16B = 8 halfs
    const int r0 = tid >> 3, c0 = tid & 7;

    auto cp_stage = [&](int s) {
        const int slot = s & 1;
        const uint32_t sbase = smem_base + slot * 49152;
        const int k0 = s * 64;
        const __half* Ap = DUAL ? (k0 < 512 ? Abase + k0 : A2base + (k0 - 512)) : (Abase + k0);
        const __half* Bp = Bbase + k0;
#pragma unroll
        for (int j = 0; j < 4; j++) {
            int row = r0 + j * 32;
            CP_ASYNC16(sbase + sw128((uint32_t)(row * 128 + c0 * 16)),
                       Ap + (long long)row * lda + c0 * 8);
        }
#pragma unroll
        for (int j = 0; j < 8; j++) {
            int row = r0 + j * 32;                 // 0..255
            uint32_t off = (j < 4) ? (16384u + sw128((uint32_t)(row * 128 + c0 * 16)))
                                   : (32768u + sw128((uint32_t)((row - 128) * 128 + c0 * 16)));
            CP_ASYNC16(sbase + off, Bp + (long long)row * ldb + c0 * 8);
        }
    };

    const int nst = K / 64;                        // 8 / 16 / 64
    for (int s = 0; s < nst; s++) {
        const int slot = s & 1;
        const uint32_t fullb = slot ? full1 : full0;
        const uint32_t freeb = slot ? free1 : free0;
        if (s >= 2) mbar_wait(freeb, ((s - 2) >> 1) & 1);   // slot free (MMA s-2 done)
        cp_stage(s);
        CP_MBAR_ARRIVE(fullb);                              // arrival when cps land
        if (wid == 0) {
            if (elect_one()) {
                mbar_wait(fullb, (s >> 1) & 1);             // tile resident
                FENCE_ASYNC();
                uint32_t aAddr = smem_base + slot * 49152;
                uint64_t ad  = make_desc(aAddr);
                uint64_t bd0 = make_desc(aAddr + 16384);
                uint64_t bd1 = make_desc(aAddr + 32768);
#pragma unroll
                for (int st = 0; st < 4; st++) {
                    uint32_t en = (s > 0 || st > 0) ? 1u : 0u;
                    mma_f16_ss(tmem,       ad + st * 2, bd0 + st * 2, IDESC_F16, en);
                    mma_f16_ss(tmem + 128, ad + st * 2, bd1 + st * 2, IDESC_F16, en);
                }
                TC_COMMIT(freeb);
            }
        }
    }
    {   // drain: last commit covers all prior MMAs of this CTA
        const int L = nst - 1;
        mbar_wait((L & 1) ? free1 : free0, (L >> 1) & 1);
    }
    TC_FENCE_AFTER();
    __syncthreads();

    // ---------------- epilogue ----------------
    float* stg = (float*)dyn_smem;                 // [128][33] staging
    float rv = 0.0f, rinv = 0.0f, psum = 0.0f, cnv = 0.0f;
    if (wid < 4) {
        int rowg = (int)(z * Mtot) + blockIdx.y * 128 + wid * 32 + lane;
        if (EPI == 1) rv = rn[rowg];
        if (EPI == 3) rinv = 1.0f / rn[rowg];
    }

#pragma unroll
    for (int ch = 0; ch < 8; ch++) {
        if (wid < 4) {
            uint32_t r[32];
            tmem_ld_x32(r, tmem + ch * 32);
            TC_WAIT_LD();
            if (EPI == 1) cnv = cn[z * N + (long long)blockIdx.x * 256 + ch * 32 + lane];
            int row = wid * 32 + lane;
#pragma unroll
            for (int c = 0; c < 32; c++) {
                float v = __uint_as_float(r[c]);
                if (EPI == 1) {
                    float cc = __shfl_sync(0xffffffffu, cnv, c);
                    v = __expf(sqrtf(fmaxf(rv + cc - 2.0f * v, 0.0f)) - 12.0f);
                    v = __half2float(__float2half_rn(v));   // sum the STORED value
                    psum += v;
                } else if (EPI == 2) {
                    v = fmaxf(v, 0.0f);
                } else if (EPI == 3) {
                    v *= rinv;
                } else if (EPI == 4) {
                    v = __half2float(__float2half_rn(v));   // rownorm of STORED fp16
                    psum += v * v;
                }
                stg[row * 33 + c] = v;
            }
        }
        __syncthreads();
#pragma unroll
        for (int it = 0; it < 16; it++) {
            int row = wid + it * 8;
            long long idx = Coff + (long long)row * N + ch * 32 + lane;
            float v = stg[row * 33 + lane];
            if (OUTH) ((__half*)gC)[idx] = __float2half_rn(v);
            else      ((float*)gC)[idx] = v;
        }
        __syncthreads();
    }
    if ((EPI == 1 || EPI == 4) && wid < 4) {
        int rowg = (int)(z * Mtot) + blockIdx.y * 128 + wid * 32 + lane;
        atomicAdd(&sum[rowg], psum);
    }

    if (tid == 0) {
        MBAR_INVAL(full0); MBAR_INVAL(full1);
        MBAR_INVAL(free0); MBAR_INVAL(free1);
    }
    __syncthreads();
    if (wid == 0) TC_DEALLOC(tmem, 256);

#else
    // ---- trivial scalar fallback (compute_103 pass only; never selected) ----
    for (int idx = tid; idx < 128 * 256; idx += 256) {
        int row = idx >> 8, col = idx & 255;
        float acc = 0.0f;
        for (int kk = 0; kk < K; kk++) {
            const __half* Ap = DUAL ? (kk < 512 ? Abase + kk : A2base + (kk - 512)) : (Abase + kk);
            float a = __half2float(Ap[(long long)row * lda]);
            float b = __half2float(Bbase[(long long)col * ldb + kk]);
            acc += a * b;
        }
        float v = acc;
        if (EPI == 1) {
            float rr = rn[z * Mtot + blockIdx.y * 128 + row];
            float cc = cn[z * N + blockIdx.x * 256 + col];
            v = __expf(sqrtf(fmaxf(rr + cc - 2.0f * v, 0.0f)) - 12.0f);
            v = __half2float(__float2half_rn(v));
            atomicAdd(&sum[z * Mtot + blockIdx.y * 128 + row], v);
        } else if (EPI == 2) v = fmaxf(v, 0.0f);
        else if (EPI == 3) v /= rn[z * Mtot + blockIdx.y * 128 + row];
        else if (EPI == 4) {
            v = __half2float(__float2half_rn(v));
            atomicAdd(&sum[z * Mtot + blockIdx.y * 128 + row], v * v);
        }
        long long o = Coff + (long long)row * N + col;
        if (OUTH) ((__half*)gC)[o] = __float2half_rn(v);
        else      ((float*)gC)[o] = v;
    }
#endif
}

// ---------------- reductions ----------------
__device__ __forceinline__ float warpReduceSum(float v) {
    v += __shfl_xor_sync(0xffffffffu, v, 16);
    v += __shfl_xor_sync(0xffffffffu, v, 8);
    v += __shfl_xor_sync(0xffffffffu, v, 4);
    v += __shfl_xor_sync(0xffffffffu, v, 2);
    v += __shfl_xor_sync(0xffffffffu, v, 1);
    return v;
}
__device__ __forceinline__ float blockAllReduceSum(float v, float* sh) {
    int lane = threadIdx.x & 31, wid = threadIdx.x >> 5;
    v = warpReduceSum(v);
    if (lane == 0) sh[wid] = v;
    __syncthreads();
    int nw = blockDim.x >> 5;
    float t = (lane < nw) ? sh[lane] : 0.0f;
    t = warpReduceSum(t);
    __syncthreads();
    return t;
}

// ---------------- fp32 -> fp16 convert ----------------
__global__ __launch_bounds__(256)
void convert_kernel(const float* __restrict__ in, __half* __restrict__ out, int n4)
{
    int i = blockIdx.x * 256 + threadIdx.x;
    if (i < n4) {
        float4 v = *(const float4*)(in + 4 * (long long)i);
        *(__half2*)(out + 4 * (long long)i)     = __floats2half2_rn(v.x, v.y);
        *(__half2*)(out + 4 * (long long)i + 2) = __floats2half2_rn(v.z, v.w);
    }
}

// ---------------- fp32 transpose -> fp16 ----------------
__global__ __launch_bounds__(256)
void transpose_kernel(const float* __restrict__ in, __half* __restrict__ out,
                      int R, int C)
{
    __shared__ float t[32][33];
    int bx = blockIdx.x * 32, by = blockIdx.y * 32;
    int x = bx + threadIdx.x;
#pragma unroll
    for (int j = 0; j < 32; j += 8)
        t[threadIdx.y + j][threadIdx.x] = in[(long long)(by + threadIdx.y + j) * C + x];
    __syncthreads();
    int x2 = by + threadIdx.x;
#pragma unroll
    for (int j = 0; j < 32; j += 8)
        out[(long long)(bx + threadIdx.y + j) * R + x2] = __float2half_rn(t[threadIdx.x][threadIdx.y + j]);
}

// ---------------- LayerNorm over D=512 (fp32 in; fp16 or fp32+res out) -----
template<int OUTH>
__global__ __launch_bounds__(128)
void layernorm_kernel(const float* __restrict__ X, const float* __restrict__ G,
                      const float* __restrict__ Bv, const float* __restrict__ R,
                      void* __restrict__ O)
{
    __shared__ float sh[32];
    long long row = blockIdx.x;
    int c = threadIdx.x * 4;
    float4 v = *(const float4*)(X + row * DD + c);

    float s = v.x + v.y + v.z + v.w;
    s = blockAllReduceSum(s, sh);
    float mu = s * (1.0f / DD);

    float d0 = v.x - mu, d1 = v.y - mu, d2 = v.z - mu, d3 = v.w - mu;
    float s2 = d0 * d0 + d1 * d1 + d2 * d2 + d3 * d3;
    s2 = blockAllReduceSum(s2, sh);
    float inv = rsqrtf(s2 * (1.0f / DD) + 1e-5f);

    float4 gg = *(const float4*)(G + c);
    float4 bb = *(const float4*)(Bv + c);
    float o0 = d0 * inv * gg.x + bb.x;
    float o1 = d1 * inv * gg.y + bb.y;
    float o2 = d2 * inv * gg.z + bb.z;
    float o3 = d3 * inv * gg.w + bb.w;
    if (R) {
        float4 rr = *(const float4*)(R + row * DD + c);
        o0 += rr.x; o1 += rr.y; o2 += rr.z; o3 += rr.w;
    }
    if (OUTH) {
        __half* Oh = (__half*)O + row * DD + c;
        *(__half2*)(Oh)     = __floats2half2_rn(o0, o1);
        *(__half2*)(Oh + 2) = __floats2half2_rn(o2, o3);
    } else {
        *(float4*)((float*)O + row * DD + c) = make_float4(o0, o1, o2, o3);
    }
}

// ======================================================================
#define SMEM_BYTES 98304   // 2 x 48KB ring -> 2 CTAs/SM

extern "C" void kernel_launch(void* const* d_in, const int* in_sizes, int n_in,
                              void* d_out, int out_size)
{
    (void)in_sizes; (void)n_in; (void)out_size;
    const float* x   = (const float*)d_in[0];
    const float* src = (const float*)d_in[1];
    const float* Wq  = (const float*)d_in[2];
    const float* Wk  = (const float*)d_in[3];
    const float* Wv  = (const float*)d_in[4];
    const float* Wm  = (const float*)d_in[5];
    const float* W1  = (const float*)d_in[6];
    const float* W2  = (const float*)d_in[7];
    const float* g1  = (const float*)d_in[8];
    const float* b1  = (const float*)d_in[9];
    const float* g2  = (const float*)d_in[10];
    const float* b2  = (const float*)d_in[11];
    float* out = (float*)d_out;

    __half *q, *k, *vT, *sc, *msg, *mln, *hid, *xr, *srcr, *wth;
    float *q2, *k2, *ssum, *mw, *ffn;
    cudaGetSymbolAddress((void**)&q,    g_q);
    cudaGetSymbolAddress((void**)&k,    g_k);
    cudaGetSymbolAddress((void**)&vT,   g_vT);
    cudaGetSymbolAddress((void**)&sc,   g_s);
    cudaGetSymbolAddress((void**)&msg,  g_msg);
    cudaGetSymbolAddress((void**)&mln,  g_mln);
    cudaGetSymbolAddress((void**)&hid,  g_hid);
    cudaGetSymbolAddress((void**)&xr,   g_xr);
    cudaGetSymbolAddress((void**)&srcr, g_srcr);
    cudaGetSymbolAddress((void**)&wth,  g_wth);
    cudaGetSymbolAddress((void**)&q2,   g_q2);
    cudaGetSymbolAddress((void**)&k2,   g_k2);
    cudaGetSymbolAddress((void**)&ssum, g_ssum);
    cudaGetSymbolAddress((void**)&mw,   g_mw);
    cudaGetSymbolAddress((void**)&ffn,  g_ffn);

    __half* WqT = wth;
    __half* WkT = wth + DD * DD;
    __half* WvT = wth + 2 * DD * DD;
    __half* WmT = wth + 3 * DD * DD;
    __half* W1T = wth + 4 * DD * DD;
    __half* W2T = wth + 8 * DD * DD;

    cudaFuncSetAttribute(tc_gemm<0,0,1>, cudaFuncAttributeMaxDynamicSharedMemorySize, SMEM_BYTES);
    cudaFuncSetAttribute(tc_gemm<0,0,0>, cudaFuncAttributeMaxDynamicSharedMemorySize, SMEM_BYTES);
    cudaFuncSetAttribute(tc_gemm<1,0,1>, cudaFuncAttributeMaxDynamicSharedMemorySize, SMEM_BYTES);
    cudaFuncSetAttribute(tc_gemm<2,1,1>, cudaFuncAttributeMaxDynamicSharedMemorySize, SMEM_BYTES);
    cudaFuncSetAttribute(tc_gemm<3,0,1>, cudaFuncAttributeMaxDynamicSharedMemorySize, SMEM_BYTES);
    cudaFuncSetAttribute(tc_gemm<4,0,1>, cudaFuncAttributeMaxDynamicSharedMemorySize, SMEM_BYTES);

    // Launch order arranged so ncu (-s 5 -c 1) captures the k-projection GEMM.
    transpose_kernel<<<dim3(16, 16), dim3(32, 8)>>>(Wq, WqT, DD, DD);        // 0
    transpose_kernel<<<dim3(16, 16), dim3(32, 8)>>>(Wk, WkT, DD, DD);        // 1
    convert_kernel<<<(NB * SSEQ * DD / 4 + 255) / 256, 256>>>(src, srcr, NB * SSEQ * DD / 4); // 2
    convert_kernel<<<(NB * LQ * DD / 4 + 255) / 256,   256>>>(x,   xr,   NB * LQ * DD / 4);   // 3
    cudaMemsetAsync(k2, 0, NB * SSEQ * sizeof(float));                       // 4
    // 5: k = srcr @ WkT  (fp16 out, fused rownorm into k2)
    tc_gemm<4,0,1><<<dim3(2, 256, 1), 256, SMEM_BYTES>>>(srcr, nullptr, WkT, k, DD, DD, DD, DD, 0, 0, 0, nullptr, nullptr, k2);

    cudaMemsetAsync(q2, 0, NB * LQ * sizeof(float));
    tc_gemm<4,0,1><<<dim3(2, 64, 1),  256, SMEM_BYTES>>>(xr,   nullptr, WqT, q, DD, DD, DD, DD, 0, 0, 0, nullptr, nullptr, q2);

    transpose_kernel<<<dim3(16, 16), dim3(32, 8)>>>(Wv, WvT, DD, DD);
    tc_gemm<0,0,1><<<dim3(SSEQ / 256, DD / 128, NB), 256, SMEM_BYTES>>>(
        WvT, nullptr, srcr, vT, SSEQ, DD, DD, DD,
        0, (long long)SSEQ * DD, (long long)DD * SSEQ, nullptr, nullptr, nullptr);

    transpose_kernel<<<dim3(16, 16), dim3(32, 8)>>>(Wm, WmT, DD, DD);
    transpose_kernel<<<dim3(32, 32), dim3(32, 8)>>>(W1, W1T, 2 * DD, 2 * DD);
    transpose_kernel<<<dim3(16, 32), dim3(32, 8)>>>(W2, W2T, 2 * DD, DD);
    cudaMemsetAsync(ssum, 0, NB * LQ * sizeof(float));

    // P_un = exp(dist - 12) fp16; row sums accumulated atomically (shift cancels)
    tc_gemm<1,0,1><<<dim3(SSEQ / 256, LQ / 128, NB), 256, SMEM_BYTES>>>(
        q, nullptr, k, sc, SSEQ, DD, DD, DD,
        (long long)LQ * DD, (long long)SSEQ * DD, (long long)LQ * SSEQ, q2, k2, ssum);

    // message = (P_un @ v) / rowsum  (fp16 out)
    tc_gemm<3,0,1><<<dim3(2, LQ / 128, NB), 256, SMEM_BYTES>>>(
        sc, nullptr, vT, msg, DD, SSEQ, SSEQ, SSEQ,
        (long long)LQ * SSEQ, (long long)DD * SSEQ, (long long)LQ * DD, ssum, nullptr, nullptr);

    // mw = message @ Wm (fp32 out); mln = LN(mw) fp16
    tc_gemm<0,0,0><<<dim3(2, 64, 1), 256, SMEM_BYTES>>>(msg, nullptr, WmT, mw, DD, DD, DD, DD, 0, 0, 0, nullptr, nullptr, nullptr);
    layernorm_kernel<1><<<NB * LQ, 128>>>(mw, g1, b1, nullptr, mln);

    // hid = relu([x, mln] @ W1) fp16
    tc_gemm<2,1,1><<<dim3(4, 64, 1), 256, SMEM_BYTES>>>(xr, mln, W1T, hid, 2 * DD, 2 * DD, DD, 2 * DD, 0, 0, 0, nullptr, nullptr, nullptr);

    // ffn = hid @ W2 (fp32 out)
    tc_gemm<0,0,0><<<dim3(2, 64, 1), 256, SMEM_BYTES>>>(hid, nullptr, W2T, ffn, DD, 2 * DD, 2 * DD, 2 * DD, 0, 0, 0, nullptr, nullptr, nullptr);

    // out = x + LN(ffn)   (residual uses ORIGINAL fp32 x)
    layernorm_kernel<0><<<NB * LQ, 128>>>(ffn, g2, b2, x, out);
}

// round 13
// speedup vs baseline: 1.0827x; 1.0827x over previous
#include <cuda_runtime.h>
#include <cuda_fp16.h>
#include <cstdint>

// Problem dims (fixed)
#define NB   8
#define LQ   1024
#define SSEQ 4096
#define DD   512

#ifndef __CUDA_ARCH_SPECIFIC__
#define __CUDA_ARCH_SPECIFIC__ 0
#endif
#if defined(__CUDA_ARCH_FEAT_SM103_ALL) || defined(__CUDA_ARCH_FEAT_SM100_ALL) || (__CUDA_ARCH_SPECIFIC__ >= 1000)
#define HAS_TCGEN05 1
#else
#define HAS_TCGEN05 0
#endif

// ---------------- static device scratch (no allocations allowed) ----------------
static __device__ __half g_q  [NB * LQ * DD];
static __device__ __half g_k  [NB * SSEQ * DD];
static __device__ __half g_vT [NB * DD * SSEQ];
static __device__ __half g_s  [NB * LQ * SSEQ];       // exp(dist-12), unnormalized
static __device__ __half g_msg[NB * LQ * DD];
static __device__ __half g_mln[NB * LQ * DD];
static __device__ __half g_hid[NB * LQ * 2 * DD];
static __device__ __half g_xr [NB * LQ * DD];
static __device__ __half g_srcr[NB * SSEQ * DD];
static __device__ __half g_wth[4 * DD * DD + 4 * DD * DD + 2 * DD * DD];
static __device__ float g_q2 [NB * LQ];
static __device__ float g_k2 [NB * SSEQ];
static __device__ float g_ssum[NB * LQ];
static __device__ float g_mw [NB * LQ * DD];
static __device__ float g_ffn[NB * LQ * DD];

// ======================= PTX helpers =======================
__device__ __forceinline__ uint32_t smem_u32(const void* p) {
    uint32_t a;
    asm("{ .reg .u64 t; cvta.to.shared.u64 t, %1; cvt.u32.u64 %0, t; }" : "=r"(a) : "l"(p));
    return a;
}
__device__ __forceinline__ uint32_t h2_bits(__half2 h) {
    return *reinterpret_cast<uint32_t*>(&h);
}
#define CP_ASYNC16(dst, src) \
    asm volatile("cp.async.cg.shared.global [%0], [%1], 16;" :: "r"(dst), "l"(src) : "memory")
#define CP_COMMIT() asm volatile("cp.async.commit_group;" ::: "memory")
#define CP_WAIT1()  asm volatile("cp.async.wait_group 1;" ::: "memory")
#define CP_WAIT0()  asm volatile("cp.async.wait_group 0;" ::: "memory")

#if HAS_TCGEN05
__device__ __forceinline__ uint32_t elect_one() {
    uint32_t pred;
    asm volatile("{\n\t.reg .pred p;\n\telect.sync _|p, 0xFFFFFFFF;\n\t"
                 "selp.b32 %0, 1, 0, p;\n\t}" : "=r"(pred));
    return pred;
}
#define MBAR_INIT(addr, cnt) \
    asm volatile("mbarrier.init.shared.b64 [%0], %1;" :: "r"(addr), "r"(cnt) : "memory")
#define MBAR_INVAL(addr) \
    asm volatile("mbarrier.inval.shared.b64 [%0];" :: "r"(addr) : "memory")
__device__ __forceinline__ void mbar_wait(uint32_t addr, uint32_t parity) {
    uint32_t done;
    asm volatile("{\n\t.reg .pred p;\n\t"
                 "mbarrier.try_wait.parity.acquire.cta.shared::cta.b64 p, [%1], %2;\n\t"
                 "selp.b32 %0, 1, 0, p;\n\t}" : "=r"(done) : "r"(addr), "r"(parity) : "memory");
    if (!done) {
        asm volatile("{\n\t.reg .pred P1;\n\t"
                     "W_%=:\n\t"
                     "mbarrier.try_wait.parity.acquire.cta.shared::cta.b64 P1, [%0], %1, 0x989680;\n\t"
                     "@P1 bra.uni D_%=;\n\t"
                     "bra.uni W_%=;\n\t"
                     "D_%=:\n\t}" :: "r"(addr), "r"(parity) : "memory");
    }
}
#define TC_ALLOC(smem_addr, n) \
    asm volatile("tcgen05.alloc.cta_group::1.sync.aligned.shared::cta.b32 [%0], %1;" \
                 :: "r"(smem_addr), "r"(n) : "memory")
#define TC_DEALLOC(tmem, n) \
    asm volatile("tcgen05.dealloc.cta_group::1.sync.aligned.b32 %0, %1;" :: "r"(tmem), "r"(n))
#define TC_RELINQ() \
    asm volatile("tcgen05.relinquish_alloc_permit.cta_group::1.sync.aligned;")
#define TC_COMMIT(mbar) \
    asm volatile("tcgen05.commit.cta_group::1.mbarrier::arrive::one.shared::cluster.b64 [%0];" \
                 :: "r"(mbar) : "memory")
#define TC_FENCE_AFTER() asm volatile("tcgen05.fence::after_thread_sync;" ::: "memory")
#define TC_WAIT_LD()     asm volatile("tcgen05.wait::ld.sync.aligned;" ::: "memory")
#define FENCE_ASYNC()    asm volatile("fence.proxy.async.shared::cta;" ::: "memory")

__device__ __forceinline__ void mma_f16_ss(uint32_t d, uint64_t a, uint64_t b,
                                           uint32_t idesc, uint32_t en) {
    asm volatile("{\n\t.reg .pred p;\n\tsetp.ne.u32 p, %4, 0;\n\t"
                 "tcgen05.mma.cta_group::1.kind::f16 [%0], %1, %2, %3, {%5,%5,%5,%5}, p;\n\t}"
                 :: "r"(d), "l"(a), "l"(b), "r"(idesc), "r"(en), "r"(0u) : "memory");
}
__device__ __forceinline__ void tmem_ld_x32(uint32_t* r, uint32_t addr) {
    asm volatile(
        "tcgen05.ld.sync.aligned.32x32b.x32.b32 "
        "{%0,%1,%2,%3,%4,%5,%6,%7,%8,%9,%10,%11,%12,%13,%14,%15,"
        "%16,%17,%18,%19,%20,%21,%22,%23,%24,%25,%26,%27,%28,%29,%30,%31}, [%32];"
        : "=r"(r[0]), "=r"(r[1]), "=r"(r[2]), "=r"(r[3]), "=r"(r[4]), "=r"(r[5]),
          "=r"(r[6]), "=r"(r[7]), "=r"(r[8]), "=r"(r[9]), "=r"(r[10]), "=r"(r[11]),
          "=r"(r[12]), "=r"(r[13]), "=r"(r[14]), "=r"(r[15]), "=r"(r[16]), "=r"(r[17]),
          "=r"(r[18]), "=r"(r[19]), "=r"(r[20]), "=r"(r[21]), "=r"(r[22]), "=r"(r[23]),
          "=r"(r[24]), "=r"(r[25]), "=r"(r[26]), "=r"(r[27]), "=r"(r[28]), "=r"(r[29]),
          "=r"(r[30]), "=r"(r[31])
        : "r"(addr));
}
__device__ __forceinline__ uint32_t sw128(uint32_t b) { return b ^ ((b >> 3) & 0x70); }
static __device__ __forceinline__ uint64_t make_desc(uint32_t addr) {
    const uint64_t base = (uint64_t(2) << 61) | (uint64_t(1) << 46)
                        | (uint64_t(64) << 32) | (uint64_t(1) << 16);
    return base | ((uint64_t)(addr >> 4) & 0x3FFF);
}
#define IDESC_F16 ((1u << 4) | ((128u / 8u) << 17) | ((128u / 16u) << 24))
#endif  // HAS_TCGEN05

// ======================================================================
// NT GEMM: C[M,N] = A[M,K] * Bt[N,K]^T; fp16 operands, fp32 accumulate.
// CTA tile 128(M) x 256(N), K chunks of 64. 2-slot ring (48KB/slot), 2 CTAs/SM.
// R10-proven mainloop: cp.async + commit-group pipeline (depth 2), one
// __syncthreads per stage, mbarrier guarding slot reuse vs MMA completion.
// Epilogue: DIRECT gmem stores (each lane owns one row x 32 consecutive cols
// = one 128B sector fp32 / 64B fp16) -- no smem staging, no extra syncs.
// EPI: 0 none, 1 exp(dist-12)+row-sum, 2 relu, 3 div-by-rn, 4 fp16+sumsq.
// OUTH: 1 fp16 out, 0 fp32 out.  DUAL: A = [gA | gA2] along K.
// ======================================================================
template<int EPI, int DUAL, int OUTH>
__global__ __launch_bounds__(256)
void tc_gemm(const __half* __restrict__ gA, const __half* __restrict__ gA2,
             const __half* __restrict__ gB, void* __restrict__ gC,
             int N, int K, int lda, int ldb,
             long long sA, long long sB, long long sC,
             const float* __restrict__ rn, const float* __restrict__ cn,
             float* __restrict__ sum)
{
    extern __shared__ __align__(1024) char dyn_smem[];

    const int tid = threadIdx.x;
    const int wid = tid >> 5, lane = tid & 31;

    const long long z = blockIdx.z;
    const __half* Abase  = gA + z * sA + (long long)blockIdx.y * 128 * lda;
    const __half* A2base = DUAL ? (gA2 + (long long)blockIdx.y * 128 * lda) : nullptr;
    const __half* Bbase  = gB + z * sB + (long long)blockIdx.x * 256 * ldb;
    const long long Coff = z * sC + (long long)blockIdx.y * 128 * N + blockIdx.x * 256;
    const int Mtot = gridDim.y * 128;

#if HAS_TCGEN05
    __shared__ uint32_t s_tmem[1];
    __shared__ __align__(8) uint64_t s_mbar[2];

    const uint32_t smem_base = smem_u32(dyn_smem);
    const uint32_t mbar_base = smem_u32(&s_mbar[0]);

    if (wid == 0) {
        TC_ALLOC(smem_u32(s_tmem), 256);
        TC_RELINQ();
    }
    if (tid == 0) { MBAR_INIT(mbar_base, 1); MBAR_INIT(mbar_base + 8, 1); }
    __syncthreads();
    const uint32_t tmem = s_tmem[0];

    // loader geometry: rows of 64 halfs = 128B, SW128; 16B = 8 halfs
    const int r0 = tid >> 3, c0 = tid & 7;

    auto cp_stage = [&](int s) {
        const int slot = s & 1;
        const uint32_t sbase = smem_base + slot * 49152;
        const int k0 = s * 64;
        const __half* Ap = DUAL ? (k0 < 512 ? Abase + k0 : A2base + (k0 - 512)) : (Abase + k0);
        const __half* Bp = Bbase + k0;
#pragma unroll
        for (int j = 0; j < 4; j++) {
            int row = r0 + j * 32;
            CP_ASYNC16(sbase + sw128((uint32_t)(row * 128 + c0 * 16)),
                       Ap + (long long)row * lda + c0 * 8);
        }
#pragma unroll
        for (int j = 0; j < 8; j++) {
            int row = r0 + j * 32;                 // 0..255
            uint32_t off = (j < 4) ? (16384u + sw128((uint32_t)(row * 128 + c0 * 16)))
                                   : (32768u + sw128((uint32_t)((row - 128) * 128 + c0 * 16)));
            CP_ASYNC16(sbase + off, Bp + (long long)row * ldb + c0 * 8);
        }
        CP_COMMIT();
    };

    const int nst = K / 64;                        // 8 / 16 / 64
    cp_stage(0);
    cp_stage(1);
    for (int s = 0; s < nst; s++) {
        const int slot = s & 1;
        if (s == nst - 1) CP_WAIT0(); else CP_WAIT1();
        __syncthreads();
        if (wid == 0) {
            FENCE_ASYNC();
            if (elect_one()) {
                uint32_t aAddr = smem_base + slot * 49152;
                uint64_t ad  = make_desc(aAddr);
                uint64_t bd0 = make_desc(aAddr + 16384);
                uint64_t bd1 = make_desc(aAddr + 32768);
#pragma unroll
                for (int st = 0; st < 4; st++) {
                    uint32_t en = (s > 0 || st > 0) ? 1u : 0u;
                    mma_f16_ss(tmem,       ad + st * 2, bd0 + st * 2, IDESC_F16, en);
                    mma_f16_ss(tmem + 128, ad + st * 2, bd1 + st * 2, IDESC_F16, en);
                }
                TC_COMMIT(mbar_base + slot * 8);
            }
        }
        if (s + 2 < nst) {
            mbar_wait(mbar_base + slot * 8, (s >> 1) & 1);
            cp_stage(s + 2);
        }
    }
    {
        const int L = nst - 1;
        mbar_wait(mbar_base + (L & 1) * 8, (L >> 1) & 1);
    }
    TC_FENCE_AFTER();

    // ---------------- epilogue: direct gmem stores ----------------
    float rv = 0.0f, rinv = 0.0f, psum = 0.0f, cnv = 0.0f;
    if (wid < 4) {
        int rowg = (int)(z * Mtot) + blockIdx.y * 128 + wid * 32 + lane;
        if (EPI == 1) rv = rn[rowg];
        if (EPI == 3) rinv = 1.0f / rn[rowg];
    }

    if (wid < 4) {
        const int row = wid * 32 + lane;
#pragma unroll
        for (int ch = 0; ch < 8; ch++) {
            uint32_t r[32];
            tmem_ld_x32(r, tmem + ch * 32);
            TC_WAIT_LD();
            if (EPI == 1) cnv = cn[z * N + (long long)blockIdx.x * 256 + ch * 32 + lane];
            float v[32];
#pragma unroll
            for (int c = 0; c < 32; c++) {
                float t = __uint_as_float(r[c]);
                if (EPI == 1) {
                    float cc = __shfl_sync(0xffffffffu, cnv, c);
                    t = __expf(sqrtf(fmaxf(rv + cc - 2.0f * t, 0.0f)) - 12.0f);
                    t = __half2float(__float2half_rn(t));   // sum the STORED value
                    psum += t;
                } else if (EPI == 2) {
                    t = fmaxf(t, 0.0f);
                } else if (EPI == 3) {
                    t *= rinv;
                } else if (EPI == 4) {
                    t = __half2float(__float2half_rn(t));   // rownorm of STORED fp16
                    psum += t * t;
                }
                v[c] = t;
            }
            const long long base = Coff + (long long)row * N + ch * 32;
            if (OUTH) {
                __half* o = (__half*)gC + base;
#pragma unroll
                for (int c = 0; c < 32; c += 8) {
                    __half2 h0 = __floats2half2_rn(v[c + 0], v[c + 1]);
                    __half2 h1 = __floats2half2_rn(v[c + 2], v[c + 3]);
                    __half2 h2 = __floats2half2_rn(v[c + 4], v[c + 5]);
                    __half2 h3 = __floats2half2_rn(v[c + 6], v[c + 7]);
                    uint4 pack;
                    pack.x = h2_bits(h0); pack.y = h2_bits(h1);
                    pack.z = h2_bits(h2); pack.w = h2_bits(h3);
                    *(uint4*)(o + c) = pack;
                }
            } else {
                float* o = (float*)gC + base;
#pragma unroll
                for (int c = 0; c < 32; c += 4)
                    *(float4*)(o + c) = make_float4(v[c], v[c + 1], v[c + 2], v[c + 3]);
            }
        }
        if (EPI == 1 || EPI == 4) {
            int rowg = (int)(z * Mtot) + blockIdx.y * 128 + row;
            atomicAdd(&sum[rowg], psum);
        }
    }
    __syncthreads();

    if (tid == 0) { MBAR_INVAL(mbar_base); MBAR_INVAL(mbar_base + 8); }
    __syncthreads();
    if (wid == 0) TC_DEALLOC(tmem, 256);

#else
    // ---- trivial scalar fallback (compute_103 pass only; never selected) ----
    for (int idx = tid; idx < 128 * 256; idx += 256) {
        int row = idx >> 8, col = idx & 255;
        float acc = 0.0f;
        for (int kk = 0; kk < K; kk++) {
            const __half* Ap = DUAL ? (kk < 512 ? Abase + kk : A2base + (kk - 512)) : (Abase + kk);
            float a = __half2float(Ap[(long long)row * lda]);
            float b = __half2float(Bbase[(long long)col * ldb + kk]);
            acc += a * b;
        }
        float v = acc;
        if (EPI == 1) {
            float rr = rn[z * Mtot + blockIdx.y * 128 + row];
            float cc = cn[z * N + blockIdx.x * 256 + col];
            v = __expf(sqrtf(fmaxf(rr + cc - 2.0f * v, 0.0f)) - 12.0f);
            v = __half2float(__float2half_rn(v));
            atomicAdd(&sum[z * Mtot + blockIdx.y * 128 + row], v);
        } else if (EPI == 2) v = fmaxf(v, 0.0f);
        else if (EPI == 3) v /= rn[z * Mtot + blockIdx.y * 128 + row];
        else if (EPI == 4) {
            v = __half2float(__float2half_rn(v));
            atomicAdd(&sum[z * Mtot + blockIdx.y * 128 + row], v * v);
        }
        long long o = Coff + (long long)row * N + col;
        if (OUTH) ((__half*)gC)[o] = __float2half_rn(v);
        else      ((float*)gC)[o] = v;
    }
#endif
}

// ---------------- reductions ----------------
__device__ __forceinline__ float warpReduceSum(float v) {
    v += __shfl_xor_sync(0xffffffffu, v, 16);
    v += __shfl_xor_sync(0xffffffffu, v, 8);
    v += __shfl_xor_sync(0xffffffffu, v, 4);
    v += __shfl_xor_sync(0xffffffffu, v, 2);
    v += __shfl_xor_sync(0xffffffffu, v, 1);
    return v;
}
__device__ __forceinline__ float blockAllReduceSum(float v, float* sh) {
    int lane = threadIdx.x & 31, wid = threadIdx.x >> 5;
    v = warpReduceSum(v);
    if (lane == 0) sh[wid] = v;
    __syncthreads();
    int nw = blockDim.x >> 5;
    float t = (lane < nw) ? sh[lane] : 0.0f;
    t = warpReduceSum(t);
    __syncthreads();
    return t;
}

// ---------------- fp32 -> fp16 convert ----------------
__global__ __launch_bounds__(256)
void convert_kernel(const float* __restrict__ in, __half* __restrict__ out, int n4)
{
    int i = blockIdx.x * 256 + threadIdx.x;
    if (i < n4) {
        float4 v = *(const float4*)(in + 4 * (long long)i);
        *(__half2*)(out + 4 * (long long)i)     = __floats2half2_rn(v.x, v.y);
        *(__half2*)(out + 4 * (long long)i + 2) = __floats2half2_rn(v.z, v.w);
    }
}

// ---------------- fp32 transpose -> fp16 ----------------
__global__ __launch_bounds__(256)
void transpose_kernel(const float* __restrict__ in, __half* __restrict__ out,
                      int R, int C)
{
    __shared__ float t[32][33];
    int bx = blockIdx.x * 32, by = blockIdx.y * 32;
    int x = bx + threadIdx.x;
#pragma unroll
    for (int j = 0; j < 32; j += 8)
        t[threadIdx.y + j][threadIdx.x] = in[(long long)(by + threadIdx.y + j) * C + x];
    __syncthreads();
    int x2 = by + threadIdx.x;
#pragma unroll
    for (int j = 0; j < 32; j += 8)
        out[(long long)(bx + threadIdx.y + j) * R + x2] = __float2half_rn(t[threadIdx.x][threadIdx.y + j]);
}

// ---------------- LayerNorm over D=512 (fp32 in; fp16 or fp32+res out) -----
template<int OUTH>
__global__ __launch_bounds__(128)
void layernorm_kernel(const float* __restrict__ X, const float* __restrict__ G,
                      const float* __restrict__ Bv, const float* __restrict__ R,
                      void* __restrict__ O)
{
    __shared__ float sh[32];
    long long row = blockIdx.x;
    int c = threadIdx.x * 4;
    float4 v = *(const float4*)(X + row * DD + c);

    float s = v.x + v.y + v.z + v.w;
    s = blockAllReduceSum(s, sh);
    float mu = s * (1.0f / DD);

    float d0 = v.x - mu, d1 = v.y - mu, d2 = v.z - mu, d3 = v.w - mu;
    float s2 = d0 * d0 + d1 * d1 + d2 * d2 + d3 * d3;
    s2 = blockAllReduceSum(s2, sh);
    float inv = rsqrtf(s2 * (1.0f / DD) + 1e-5f);

    float4 gg = *(const float4*)(G + c);
    float4 bb = *(const float4*)(Bv + c);
    float o0 = d0 * inv * gg.x + bb.x;
    float o1 = d1 * inv * gg.y + bb.y;
    float o2 = d2 * inv * gg.z + bb.z;
    float o3 = d3 * inv * gg.w + bb.w;
    if (R) {
        float4 rr = *(const float4*)(R + row * DD + c);
        o0 += rr.x; o1 += rr.y; o2 += rr.z; o3 += rr.w;
    }
    if (OUTH) {
        __half* Oh = (__half*)O + row * DD + c;
        *(__half2*)(Oh)     = __floats2half2_rn(o0, o1);
        *(__half2*)(Oh + 2) = __floats2half2_rn(o2, o3);
    } else {
        *(float4*)((float*)O + row * DD + c) = make_float4(o0, o1, o2, o3);
    }
}

// ======================================================================
#define SMEM_BYTES 98304   // 2 x 48KB ring -> 2 CTAs/SM

extern "C" void kernel_launch(void* const* d_in, const int* in_sizes, int n_in,
                              void* d_out, int out_size)
{
    (void)in_sizes; (void)n_in; (void)out_size;
    const float* x   = (const float*)d_in[0];
    const float* src = (const float*)d_in[1];
    const float* Wq  = (const float*)d_in[2];
    const float* Wk  = (const float*)d_in[3];
    const float* Wv  = (const float*)d_in[4];
    const float* Wm  = (const float*)d_in[5];
    const float* W1  = (const float*)d_in[6];
    const float* W2  = (const float*)d_in[7];
    const float* g1  = (const float*)d_in[8];
    const float* b1  = (const float*)d_in[9];
    const float* g2  = (const float*)d_in[10];
    const float* b2  = (const float*)d_in[11];
    float* out = (float*)d_out;

    __half *q, *k, *vT, *sc, *msg, *mln, *hid, *xr, *srcr, *wth;
    float *q2, *k2, *ssum, *mw, *ffn;
    cudaGetSymbolAddress((void**)&q,    g_q);
    cudaGetSymbolAddress((void**)&k,    g_k);
    cudaGetSymbolAddress((void**)&vT,   g_vT);
    cudaGetSymbolAddress((void**)&sc,   g_s);
    cudaGetSymbolAddress((void**)&msg,  g_msg);
    cudaGetSymbolAddress((void**)&mln,  g_mln);
    cudaGetSymbolAddress((void**)&hid,  g_hid);
    cudaGetSymbolAddress((void**)&xr,   g_xr);
    cudaGetSymbolAddress((void**)&srcr, g_srcr);
    cudaGetSymbolAddress((void**)&wth,  g_wth);
    cudaGetSymbolAddress((void**)&q2,   g_q2);
    cudaGetSymbolAddress((void**)&k2,   g_k2);
    cudaGetSymbolAddress((void**)&ssum, g_ssum);
    cudaGetSymbolAddress((void**)&mw,   g_mw);
    cudaGetSymbolAddress((void**)&ffn,  g_ffn);

    __half* WqT = wth;
    __half* WkT = wth + DD * DD;
    __half* WvT = wth + 2 * DD * DD;
    __half* WmT = wth + 3 * DD * DD;
    __half* W1T = wth + 4 * DD * DD;
    __half* W2T = wth + 8 * DD * DD;

    cudaFuncSetAttribute(tc_gemm<0,0,1>, cudaFuncAttributeMaxDynamicSharedMemorySize, SMEM_BYTES);
    cudaFuncSetAttribute(tc_gemm<0,0,0>, cudaFuncAttributeMaxDynamicSharedMemorySize, SMEM_BYTES);
    cudaFuncSetAttribute(tc_gemm<1,0,1>, cudaFuncAttributeMaxDynamicSharedMemorySize, SMEM_BYTES);
    cudaFuncSetAttribute(tc_gemm<2,1,1>, cudaFuncAttributeMaxDynamicSharedMemorySize, SMEM_BYTES);
    cudaFuncSetAttribute(tc_gemm<3,0,1>, cudaFuncAttributeMaxDynamicSharedMemorySize, SMEM_BYTES);
    cudaFuncSetAttribute(tc_gemm<4,0,1>, cudaFuncAttributeMaxDynamicSharedMemorySize, SMEM_BYTES);

    // Launch order arranged so ncu (-s 5 -c 1) captures the k-projection GEMM.
    transpose_kernel<<<dim3(16, 16), dim3(32, 8)>>>(Wq, WqT, DD, DD);        // 0
    transpose_kernel<<<dim3(16, 16), dim3(32, 8)>>>(Wk, WkT, DD, DD);        // 1
    convert_kernel<<<(NB * SSEQ * DD / 4 + 255) / 256, 256>>>(src, srcr, NB * SSEQ * DD / 4); // 2
    convert_kernel<<<(NB * LQ * DD / 4 + 255) / 256,   256>>>(x,   xr,   NB * LQ * DD / 4);   // 3
    cudaMemsetAsync(k2, 0, NB * SSEQ * sizeof(float));                       // 4
    // 5: k = srcr @ WkT  (fp16 out, fused rownorm into k2)
    tc_gemm<4,0,1><<<dim3(2, 256, 1), 256, SMEM_BYTES>>>(srcr, nullptr, WkT, k, DD, DD, DD, DD, 0, 0, 0, nullptr, nullptr, k2);

    cudaMemsetAsync(q2, 0, NB * LQ * sizeof(float));
    tc_gemm<4,0,1><<<dim3(2, 64, 1),  256, SMEM_BYTES>>>(xr,   nullptr, WqT, q, DD, DD, DD, DD, 0, 0, 0, nullptr, nullptr, q2);

    transpose_kernel<<<dim3(16, 16), dim3(32, 8)>>>(Wv, WvT, DD, DD);
    tc_gemm<0,0,1><<<dim3(SSEQ / 256, DD / 128, NB), 256, SMEM_BYTES>>>(
        WvT, nullptr, srcr, vT, SSEQ, DD, DD, DD,
        0, (long long)SSEQ * DD, (long long)DD * SSEQ, nullptr, nullptr, nullptr);

    transpose_kernel<<<dim3(16, 16), dim3(32, 8)>>>(Wm, WmT, DD, DD);
    transpose_kernel<<<dim3(32, 32), dim3(32, 8)>>>(W1, W1T, 2 * DD, 2 * DD);
    transpose_kernel<<<dim3(16, 32), dim3(32, 8)>>>(W2, W2T, 2 * DD, DD);
    cudaMemsetAsync(ssum, 0, NB * LQ * sizeof(float));

    // P_un = exp(dist - 12) fp16; row sums accumulated atomically (shift cancels)
    tc_gemm<1,0,1><<<dim3(SSEQ / 256, LQ / 128, NB), 256, SMEM_BYTES>>>(
        q, nullptr, k, sc, SSEQ, DD, DD, DD,
        (long long)LQ * DD, (long long)SSEQ * DD, (long long)LQ * SSEQ, q2, k2, ssum);

    // message = (P_un @ v) / rowsum  (fp16 out)
    tc_gemm<3,0,1><<<dim3(2, LQ / 128, NB), 256, SMEM_BYTES>>>(
        sc, nullptr, vT, msg, DD, SSEQ, SSEQ, SSEQ,
        (long long)LQ * SSEQ, (long long)DD * SSEQ, (long long)LQ * DD, ssum, nullptr, nullptr);

    // mw = message @ Wm (fp32 out); mln = LN(mw) fp16
    tc_gemm<0,0,0><<<dim3(2, 64, 1), 256, SMEM_BYTES>>>(msg, nullptr, WmT, mw, DD, DD, DD, DD, 0, 0, 0, nullptr, nullptr, nullptr);
    layernorm_kernel<1><<<NB * LQ, 128>>>(mw, g1, b1, nullptr, mln);

    // hid = relu([x, mln] @ W1) fp16
    tc_gemm<2,1,1><<<dim3(4, 64, 1), 256, SMEM_BYTES>>>(xr, mln, W1T, hid, 2 * DD, 2 * DD, DD, 2 * DD, 0, 0, 0, nullptr, nullptr, nullptr);

    // ffn = hid @ W2 (fp32 out)
    tc_gemm<0,0,0><<<dim3(2, 64, 1), 256, SMEM_BYTES>>>(hid, nullptr, W2T, ffn, DD, 2 * DD, 2 * DD, 2 * DD, 0, 0, 0, nullptr, nullptr, nullptr);

    // out = x + LN(ffn)   (residual uses ORIGINAL fp32 x)
    layernorm_kernel<0><<<NB * LQ, 128>>>(ffn, g2, b2, x, out);
}

// round 16
// speedup vs baseline: 1.0999x; 1.0159x over previous
#include <cuda_runtime.h>
#include <cuda_fp16.h>
#include <cstdint>

// Problem dims (fixed)
#define NB   8
#define LQ   1024
#define SSEQ 4096
#define DD   512

#ifndef __CUDA_ARCH_SPECIFIC__
#define __CUDA_ARCH_SPECIFIC__ 0
#endif
#if defined(__CUDA_ARCH_FEAT_SM103_ALL) || defined(__CUDA_ARCH_FEAT_SM100_ALL) || (__CUDA_ARCH_SPECIFIC__ >= 1000)
#define HAS_TCGEN05 1
#else
#define HAS_TCGEN05 0
#endif

// ---------------- static device scratch (no allocations allowed) ----------------
static __device__ __half g_q  [NB * LQ * DD];
static __device__ __half g_k  [NB * SSEQ * DD];
static __device__ __half g_vT [NB * DD * SSEQ];
static __device__ __half g_s  [NB * LQ * SSEQ];       // exp(dist-12), unnormalized
static __device__ __half g_msg[NB * LQ * DD];
static __device__ __half g_mln[NB * LQ * DD];
static __device__ __half g_hid[NB * LQ * 2 * DD];
static __device__ __half g_xr [NB * LQ * DD];
static __device__ __half g_srcr[NB * SSEQ * DD];
static __device__ __half g_wth[4 * DD * DD + 4 * DD * DD + 2 * DD * DD];
static __device__ float g_q2 [NB * LQ];
static __device__ float g_k2 [NB * SSEQ];
static __device__ float g_ssum[NB * LQ];
static __device__ float g_mw [NB * LQ * DD];
static __device__ float g_ffn[NB * LQ * DD];

// ======================= PTX helpers =======================
__device__ __forceinline__ uint32_t smem_u32(const void* p) {
    uint32_t a;
    asm("{ .reg .u64 t; cvta.to.shared.u64 t, %1; cvt.u32.u64 %0, t; }" : "=r"(a) : "l"(p));
    return a;
}
__device__ __forceinline__ uint32_t h2_bits(__half2 h) {
    return *reinterpret_cast<uint32_t*>(&h);
}
#define CP_ASYNC16(dst, src) \
    asm volatile("cp.async.cg.shared.global [%0], [%1], 16;" :: "r"(dst), "l"(src) : "memory")
#define CP_COMMIT() asm volatile("cp.async.commit_group;" ::: "memory")
#define CP_WAIT1()  asm volatile("cp.async.wait_group 1;" ::: "memory")
#define CP_WAIT0()  asm volatile("cp.async.wait_group 0;" ::: "memory")

#if HAS_TCGEN05
__device__ __forceinline__ uint32_t elect_one() {
    uint32_t pred;
    asm volatile("{\n\t.reg .pred p;\n\telect.sync _|p, 0xFFFFFFFF;\n\t"
                 "selp.b32 %0, 1, 0, p;\n\t}" : "=r"(pred));
    return pred;
}
#define MBAR_INIT(addr, cnt) \
    asm volatile("mbarrier.init.shared.b64 [%0], %1;" :: "r"(addr), "r"(cnt) : "memory")
#define MBAR_INVAL(addr) \
    asm volatile("mbarrier.inval.shared.b64 [%0];" :: "r"(addr) : "memory")
__device__ __forceinline__ void mbar_wait(uint32_t addr, uint32_t parity) {
    uint32_t done;
    asm volatile("{\n\t.reg .pred p;\n\t"
                 "mbarrier.try_wait.parity.acquire.cta.shared::cta.b64 p, [%1], %2;\n\t"
                 "selp.b32 %0, 1, 0, p;\n\t}" : "=r"(done) : "r"(addr), "r"(parity) : "memory");
    if (!done) {
        asm volatile("{\n\t.reg .pred P1;\n\t"
                     "W_%=:\n\t"
                     "mbarrier.try_wait.parity.acquire.cta.shared::cta.b64 P1, [%0], %1, 0x989680;\n\t"
                     "@P1 bra.uni D_%=;\n\t"
                     "bra.uni W_%=;\n\t"
                     "D_%=:\n\t}" :: "r"(addr), "r"(parity) : "memory");
    }
}
#define TC_ALLOC(smem_addr, n) \
    asm volatile("tcgen05.alloc.cta_group::1.sync.aligned.shared::cta.b32 [%0], %1;" \
                 :: "r"(smem_addr), "r"(n) : "memory")
#define TC_DEALLOC(tmem, n) \
    asm volatile("tcgen05.dealloc.cta_group::1.sync.aligned.b32 %0, %1;" :: "r"(tmem), "r"(n))
#define TC_RELINQ() \
    asm volatile("tcgen05.relinquish_alloc_permit.cta_group::1.sync.aligned;")
#define TC_COMMIT(mbar) \
    asm volatile("tcgen05.commit.cta_group::1.mbarrier::arrive::one.shared::cluster.b64 [%0];" \
                 :: "r"(mbar) : "memory")
#define TC_FENCE_AFTER() asm volatile("tcgen05.fence::after_thread_sync;" ::: "memory")
#define TC_WAIT_LD()     asm volatile("tcgen05.wait::ld.sync.aligned;" ::: "memory")
#define FENCE_ASYNC()    asm volatile("fence.proxy.async.shared::cta;" ::: "memory")

__device__ __forceinline__ void mma_f16_ss(uint32_t d, uint64_t a, uint64_t b,
                                           uint32_t idesc, uint32_t en) {
    asm volatile("{\n\t.reg .pred p;\n\tsetp.ne.u32 p, %4, 0;\n\t"
                 "tcgen05.mma.cta_group::1.kind::f16 [%0], %1, %2, %3, {%5,%5,%5,%5}, p;\n\t}"
                 :: "r"(d), "l"(a), "l"(b), "r"(idesc), "r"(en), "r"(0u) : "memory");
}
__device__ __forceinline__ void tmem_ld_x32(uint32_t* r, uint32_t addr) {
    asm volatile(
        "tcgen05.ld.sync.aligned.32x32b.x32.b32 "
        "{%0,%1,%2,%3,%4,%5,%6,%7,%8,%9,%10,%11,%12,%13,%14,%15,"
        "%16,%17,%18,%19,%20,%21,%22,%23,%24,%25,%26,%27,%28,%29,%30,%31}, [%32];"
        : "=r"(r[0]), "=r"(r[1]), "=r"(r[2]), "=r"(r[3]), "=r"(r[4]), "=r"(r[5]),
          "=r"(r[6]), "=r"(r[7]), "=r"(r[8]), "=r"(r[9]), "=r"(r[10]), "=r"(r[11]),
          "=r"(r[12]), "=r"(r[13]), "=r"(r[14]), "=r"(r[15]), "=r"(r[16]), "=r"(r[17]),
          "=r"(r[18]), "=r"(r[19]), "=r"(r[20]), "=r"(r[21]), "=r"(r[22]), "=r"(r[23]),
          "=r"(r[24]), "=r"(r[25]), "=r"(r[26]), "=r"(r[27]), "=r"(r[28]), "=r"(r[29]),
          "=r"(r[30]), "=r"(r[31])
        : "r"(addr));
}
__device__ __forceinline__ uint32_t sw128(uint32_t b) { return b ^ ((b >> 3) & 0x70); }
static __device__ __forceinline__ uint64_t make_desc(uint32_t addr) {
    const uint64_t base = (uint64_t(2) << 61) | (uint64_t(1) << 46)
                        | (uint64_t(64) << 32) | (uint64_t(1) << 16);
    return base | ((uint64_t)(addr >> 4) & 0x3FFF);
}
#define IDESC_F16 ((1u << 4) | ((128u / 8u) << 17) | ((128u / 16u) << 24))
#endif  // HAS_TCGEN05

// ======================================================================
// NT GEMM: C[M,N] = A[M,K] * Bt[N,K]^T; fp16 operands, fp32 accumulate.
// CTA tile 128(M) x (NH*128)(N), K chunks of 64. 2-slot ring
// (slot = A 16KB + NH x B 16KB), so NH=2 -> 2 CTAs/SM, NH=1 -> 3 CTAs/SM.
// R10-proven mainloop: cp.async + commit-group pipeline (depth 2), one
// __syncthreads per stage, mbarrier guarding slot reuse vs MMA completion.
// Epilogue: direct coalesced gmem stores (lane owns row x 32 consecutive cols).
// EPI: 0 none, 1 exp(dist-12)+row-sum, 2 relu, 3 div-by-rn, 4 fp16+sumsq.
// OUTH: 1 fp16 out, 0 fp32 out.  DUAL: A = [gA | gA2] along K.
// ======================================================================
template<int EPI, int DUAL, int OUTH, int NH>
__global__ __launch_bounds__(256)
void tc_gemm(const __half* __restrict__ gA, const __half* __restrict__ gA2,
             const __half* __restrict__ gB, void* __restrict__ gC,
             int N, int K, int lda, int ldb,
             long long sA, long long sB, long long sC,
             const float* __restrict__ rn, const float* __restrict__ cn,
             float* __restrict__ sum)
{
    extern __shared__ __align__(1024) char dyn_smem[];

    const int TILE_N = NH * 128;
    const int SLOT   = 16384 * (1 + NH);

    const int tid = threadIdx.x;
    const int wid = tid >> 5, lane = tid & 31;

    const long long z = blockIdx.z;
    const __half* Abase  = gA + z * sA + (long long)blockIdx.y * 128 * lda;
    const __half* A2base = DUAL ? (gA2 + (long long)blockIdx.y * 128 * lda) : nullptr;
    const __half* Bbase  = gB + z * sB + (long long)blockIdx.x * TILE_N * ldb;
    const long long Coff = z * sC + (long long)blockIdx.y * 128 * N + blockIdx.x * TILE_N;
    const int Mtot = gridDim.y * 128;

#if HAS_TCGEN05
    __shared__ uint32_t s_tmem[1];
    __shared__ __align__(8) uint64_t s_mbar[2];

    const uint32_t smem_base = smem_u32(dyn_smem);
    const uint32_t mbar_base = smem_u32(&s_mbar[0]);

    if (wid == 0) {
        TC_ALLOC(smem_u32(s_tmem), NH * 128);
        TC_RELINQ();
    }
    if (tid == 0) { MBAR_INIT(mbar_base, 1); MBAR_INIT(mbar_base + 8, 1); }
    __syncthreads();
    const uint32_t tmem = s_tmem[0];

    // loader geometry: rows of 64 halfs = 128B, SW128; 16B = 8 halfs
    const int r0 = tid >> 3, c0 = tid & 7;

    auto cp_stage = [&](int s) {
        const int slot = s & 1;
        const uint32_t sbase = smem_base + slot * SLOT;
        const int k0 = s * 64;
        const __half* Ap = DUAL ? (k0 < 512 ? Abase + k0 : A2base + (k0 - 512)) : (Abase + k0);
        const __half* Bp = Bbase + k0;
#pragma unroll
        for (int j = 0; j < 4; j++) {
            int row = r0 + j * 32;
            CP_ASYNC16(sbase + sw128((uint32_t)(row * 128 + c0 * 16)),
                       Ap + (long long)row * lda + c0 * 8);
        }
#pragma unroll
        for (int j = 0; j < 4 * NH; j++) {
            int row = r0 + j * 32;                 // 0..TILE_N-1
            int half = row >> 7;                   // which 128-row B block
            int rloc = row & 127;
            uint32_t off = (uint32_t)(16384 * (1 + half))
                         + sw128((uint32_t)(rloc * 128 + c0 * 16));
            CP_ASYNC16(sbase + off, Bp + (long long)row * ldb + c0 * 8);
        }
        CP_COMMIT();
    };

    const int nst = K / 64;                        // 8 / 16 / 64
    cp_stage(0);
    cp_stage(1);
    for (int s = 0; s < nst; s++) {
        const int slot = s & 1;
        if (s == nst - 1) CP_WAIT0(); else CP_WAIT1();
        __syncthreads();
        if (wid == 0) {
            FENCE_ASYNC();
            if (elect_one()) {
                uint32_t aAddr = smem_base + slot * SLOT;
                uint64_t ad = make_desc(aAddr);
#pragma unroll
                for (int st = 0; st < 4; st++) {
                    uint32_t en = (s > 0 || st > 0) ? 1u : 0u;
#pragma unroll
                    for (int h = 0; h < NH; h++) {
                        uint64_t bd = make_desc(aAddr + 16384 * (1 + h));
                        mma_f16_ss(tmem + h * 128, ad + st * 2, bd + st * 2, IDESC_F16, en);
                    }
                }
                TC_COMMIT(mbar_base + slot * 8);
            }
        }
        if (s + 2 < nst) {
            mbar_wait(mbar_base + slot * 8, (s >> 1) & 1);
            cp_stage(s + 2);
        }
    }
    {
        const int L = nst - 1;
        mbar_wait(mbar_base + (L & 1) * 8, (L >> 1) & 1);
    }
    TC_FENCE_AFTER();

    // ---------------- epilogue: direct gmem stores ----------------
    float rv = 0.0f, rinv = 0.0f, psum = 0.0f, cnv = 0.0f;
    if (wid < 4) {
        int rowg = (int)(z * Mtot) + blockIdx.y * 128 + wid * 32 + lane;
        if (EPI == 1) rv = rn[rowg];
        if (EPI == 3) rinv = 1.0f / rn[rowg];
    }

    if (wid < 4) {
        const int row = wid * 32 + lane;
#pragma unroll
        for (int ch = 0; ch < 4 * NH; ch++) {
            uint32_t r[32];
            tmem_ld_x32(r, tmem + ch * 32);
            TC_WAIT_LD();
            if (EPI == 1) cnv = cn[z * N + (long long)blockIdx.x * TILE_N + ch * 32 + lane];
            float v[32];
#pragma unroll
            for (int c = 0; c < 32; c++) {
                float t = __uint_as_float(r[c]);
                if (EPI == 1) {
                    float cc = __shfl_sync(0xffffffffu, cnv, c);
                    t = __expf(sqrtf(fmaxf(rv + cc - 2.0f * t, 0.0f)) - 12.0f);
                    t = __half2float(__float2half_rn(t));   // sum the STORED value
                    psum += t;
                } else if (EPI == 2) {
                    t = fmaxf(t, 0.0f);
                } else if (EPI == 3) {
                    t *= rinv;
                } else if (EPI == 4) {
                    t = __half2float(__float2half_rn(t));   // rownorm of STORED fp16
                    psum += t * t;
                }
                v[c] = t;
            }
            const long long base = Coff + (long long)row * N + ch * 32;
            if (OUTH) {
                __half* o = (__half*)gC + base;
#pragma unroll
                for (int c = 0; c < 32; c += 8) {
                    __half2 h0 = __floats2half2_rn(v[c + 0], v[c + 1]);
                    __half2 h1 = __floats2half2_rn(v[c + 2], v[c + 3]);
                    __half2 h2 = __floats2half2_rn(v[c + 4], v[c + 5]);
                    __half2 h3 = __floats2half2_rn(v[c + 6], v[c + 7]);
                    uint4 pack;
                    pack.x = h2_bits(h0); pack.y = h2_bits(h1);
                    pack.z = h2_bits(h2); pack.w = h2_bits(h3);
                    *(uint4*)(o + c) = pack;
                }
            } else {
                float* o = (float*)gC + base;
#pragma unroll
                for (int c = 0; c < 32; c += 4)
                    *(float4*)(o + c) = make_float4(v[c], v[c + 1], v[c + 2], v[c + 3]);
            }
        }
        if (EPI == 1 || EPI == 4) {
            int rowg = (int)(z * Mtot) + blockIdx.y * 128 + row;
            atomicAdd(&sum[rowg], psum);
        }
    }
    __syncthreads();

    if (tid == 0) { MBAR_INVAL(mbar_base); MBAR_INVAL(mbar_base + 8); }
    __syncthreads();
    if (wid == 0) TC_DEALLOC(tmem, NH * 128);

#else
    // ---- trivial scalar fallback (compute_103 pass only; never selected) ----
    const int TILE = 128 * TILE_N;
    for (int idx = tid; idx < TILE; idx += 256) {
        int row = idx / TILE_N, col = idx % TILE_N;
        float acc = 0.0f;
        for (int kk = 0; kk < K; kk++) {
            const __half* Ap = DUAL ? (kk < 512 ? Abase + kk : A2base + (kk - 512)) : (Abase + kk);
            float a = __half2float(Ap[(long long)row * lda]);
            float b = __half2float(Bbase[(long long)col * ldb + kk]);
            acc += a * b;
        }
        float v = acc;
        if (EPI == 1) {
            float rr = rn[z * Mtot + blockIdx.y * 128 + row];
            float cc = cn[z * N + blockIdx.x * TILE_N + col];
            v = __expf(sqrtf(fmaxf(rr + cc - 2.0f * v, 0.0f)) - 12.0f);
            v = __half2float(__float2half_rn(v));
            atomicAdd(&sum[z * Mtot + blockIdx.y * 128 + row], v);
        } else if (EPI == 2) v = fmaxf(v, 0.0f);
        else if (EPI == 3) v /= rn[z * Mtot + blockIdx.y * 128 + row];
        else if (EPI == 4) {
            v = __half2float(__float2half_rn(v));
            atomicAdd(&sum[z * Mtot + blockIdx.y * 128 + row], v * v);
        }
        long long o = Coff + (long long)row * N + col;
        if (OUTH) ((__half*)gC)[o] = __float2half_rn(v);
        else      ((float*)gC)[o] = v;
    }
#endif
}

// ---------------- reductions ----------------
__device__ __forceinline__ float warpReduceSum(float v) {
    v += __shfl_xor_sync(0xffffffffu, v, 16);
    v += __shfl_xor_sync(0xffffffffu, v, 8);
    v += __shfl_xor_sync(0xffffffffu, v, 4);
    v += __shfl_xor_sync(0xffffffffu, v, 2);
    v += __shfl_xor_sync(0xffffffffu, v, 1);
    return v;
}
__device__ __forceinline__ float blockAllReduceSum(float v, float* sh) {
    int lane = threadIdx.x & 31, wid = threadIdx.x >> 5;
    v = warpReduceSum(v);
    if (lane == 0) sh[wid] = v;
    __syncthreads();
    int nw = blockDim.x >> 5;
    float t = (lane < nw) ? sh[lane] : 0.0f;
    t = warpReduceSum(t);
    __syncthreads();
    return t;
}

// ---------------- fp32 -> fp16 convert ----------------
__global__ __launch_bounds__(256)
void convert_kernel(const float* __restrict__ in, __half* __restrict__ out, int n4)
{
    int i = blockIdx.x * 256 + threadIdx.x;
    if (i < n4) {
        float4 v = *(const float4*)(in + 4 * (long long)i);
        *(__half2*)(out + 4 * (long long)i)     = __floats2half2_rn(v.x, v.y);
        *(__half2*)(out + 4 * (long long)i + 2) = __floats2half2_rn(v.z, v.w);
    }
}

// ---------------- fp32 transpose -> fp16 ----------------
__global__ __launch_bounds__(256)
void transpose_kernel(const float* __restrict__ in, __half* __restrict__ out,
                      int R, int C)
{
    __shared__ float t[32][33];
    int bx = blockIdx.x * 32, by = blockIdx.y * 32;
    int x = bx + threadIdx.x;
#pragma unroll
    for (int j = 0; j < 32; j += 8)
        t[threadIdx.y + j][threadIdx.x] = in[(long long)(by + threadIdx.y + j) * C + x];
    __syncthreads();
    int x2 = by + threadIdx.x;
#pragma unroll
    for (int j = 0; j < 32; j += 8)
        out[(long long)(bx + threadIdx.y + j) * R + x2] = __float2half_rn(t[threadIdx.x][threadIdx.y + j]);
}

// ---------------- LayerNorm over D=512 (fp32 in; fp16 or fp32+res out) -----
template<int OUTH>
__global__ __launch_bounds__(128)
void layernorm_kernel(const float* __restrict__ X, const float* __restrict__ G,
                      const float* __restrict__ Bv, const float* __restrict__ R,
                      void* __restrict__ O)
{
    __shared__ float sh[32];
    long long row = blockIdx.x;
    int c = threadIdx.x * 4;
    float4 v = *(const float4*)(X + row * DD + c);

    float s = v.x + v.y + v.z + v.w;
    s = blockAllReduceSum(s, sh);
    float mu = s * (1.0f / DD);

    float d0 = v.x - mu, d1 = v.y - mu, d2 = v.z - mu, d3 = v.w - mu;
    float s2 = d0 * d0 + d1 * d1 + d2 * d2 + d3 * d3;
    s2 = blockAllReduceSum(s2, sh);
    float inv = rsqrtf(s2 * (1.0f / DD) + 1e-5f);

    float4 gg = *(const float4*)(G + c);
    float4 bb = *(const float4*)(Bv + c);
    float o0 = d0 * inv * gg.x + bb.x;
    float o1 = d1 * inv * gg.y + bb.y;
    float o2 = d2 * inv * gg.z + bb.z;
    float o3 = d3 * inv * gg.w + bb.w;
    if (R) {
        float4 rr = *(const float4*)(R + row * DD + c);
        o0 += rr.x; o1 += rr.y; o2 += rr.z; o3 += rr.w;
    }
    if (OUTH) {
        __half* Oh = (__half*)O + row * DD + c;
        *(__half2*)(Oh)     = __floats2half2_rn(o0, o1);
        *(__half2*)(Oh + 2) = __floats2half2_rn(o2, o3);
    } else {
        *(float4*)((float*)O + row * DD + c) = make_float4(o0, o1, o2, o3);
    }
}

// ======================================================================
#define SMEM_N2 98304   // 2 x 48KB ring (NH=2) -> 2 CTAs/SM
#define SMEM_N1 65536   // 2 x 32KB ring (NH=1) -> 3 CTAs/SM

extern "C" void kernel_launch(void* const* d_in, const int* in_sizes, int n_in,
                              void* d_out, int out_size)
{
    (void)in_sizes; (void)n_in; (void)out_size;
    const float* x   = (const float*)d_in[0];
    const float* src = (const float*)d_in[1];
    const float* Wq  = (const float*)d_in[2];
    const float* Wk  = (const float*)d_in[3];
    const float* Wv  = (const float*)d_in[4];
    const float* Wm  = (const float*)d_in[5];
    const float* W1  = (const float*)d_in[6];
    const float* W2  = (const float*)d_in[7];
    const float* g1  = (const float*)d_in[8];
    const float* b1  = (const float*)d_in[9];
    const float* g2  = (const float*)d_in[10];
    const float* b2  = (const float*)d_in[11];
    float* out = (float*)d_out;

    __half *q, *k, *vT, *sc, *msg, *mln, *hid, *xr, *srcr, *wth;
    float *q2, *k2, *ssum, *mw, *ffn;
    cudaGetSymbolAddress((void**)&q,    g_q);
    cudaGetSymbolAddress((void**)&k,    g_k);
    cudaGetSymbolAddress((void**)&vT,   g_vT);
    cudaGetSymbolAddress((void**)&sc,   g_s);
    cudaGetSymbolAddress((void**)&msg,  g_msg);
    cudaGetSymbolAddress((void**)&mln,  g_mln);
    cudaGetSymbolAddress((void**)&hid,  g_hid);
    cudaGetSymbolAddress((void**)&xr,   g_xr);
    cudaGetSymbolAddress((void**)&srcr, g_srcr);
    cudaGetSymbolAddress((void**)&wth,  g_wth);
    cudaGetSymbolAddress((void**)&q2,   g_q2);
    cudaGetSymbolAddress((void**)&k2,   g_k2);
    cudaGetSymbolAddress((void**)&ssum, g_ssum);
    cudaGetSymbolAddress((void**)&mw,   g_mw);
    cudaGetSymbolAddress((void**)&ffn,  g_ffn);

    __half* WqT = wth;
    __half* WkT = wth + DD * DD;
    __half* WvT = wth + 2 * DD * DD;
    __half* WmT = wth + 3 * DD * DD;
    __half* W1T = wth + 4 * DD * DD;
    __half* W2T = wth + 8 * DD * DD;

    cudaFuncSetAttribute(tc_gemm<4,0,1,2>, cudaFuncAttributeMaxDynamicSharedMemorySize, SMEM_N2);
    cudaFuncSetAttribute(tc_gemm<4,0,1,1>, cudaFuncAttributeMaxDynamicSharedMemorySize, SMEM_N1);
    cudaFuncSetAttribute(tc_gemm<0,0,1,2>, cudaFuncAttributeMaxDynamicSharedMemorySize, SMEM_N2);
    cudaFuncSetAttribute(tc_gemm<1,0,1,2>, cudaFuncAttributeMaxDynamicSharedMemorySize, SMEM_N2);
    cudaFuncSetAttribute(tc_gemm<3,0,1,1>, cudaFuncAttributeMaxDynamicSharedMemorySize, SMEM_N1);
    cudaFuncSetAttribute(tc_gemm<0,0,0,1>, cudaFuncAttributeMaxDynamicSharedMemorySize, SMEM_N1);
    cudaFuncSetAttribute(tc_gemm<2,1,1,1>, cudaFuncAttributeMaxDynamicSharedMemorySize, SMEM_N1);

    // Launch order arranged so ncu (-s 5 -c 1) captures the k-projection GEMM.
    transpose_kernel<<<dim3(16, 16), dim3(32, 8)>>>(Wq, WqT, DD, DD);        // 0
    transpose_kernel<<<dim3(16, 16), dim3(32, 8)>>>(Wk, WkT, DD, DD);        // 1
    convert_kernel<<<(NB * SSEQ * DD / 4 + 255) / 256, 256>>>(src, srcr, NB * SSEQ * DD / 4); // 2
    convert_kernel<<<(NB * LQ * DD / 4 + 255) / 256,   256>>>(x,   xr,   NB * LQ * DD / 4);   // 3
    cudaMemsetAsync(k2, 0, NB * SSEQ * sizeof(float));                       // 4
    // 5: k = srcr @ WkT  (fp16 out, fused rownorm into k2)
    tc_gemm<4,0,1,2><<<dim3(2, 256, 1), 256, SMEM_N2>>>(srcr, nullptr, WkT, k, DD, DD, DD, DD, 0, 0, 0, nullptr, nullptr, k2);

    cudaMemsetAsync(q2, 0, NB * LQ * sizeof(float));
    tc_gemm<4,0,1,1><<<dim3(4, 64, 1),  256, SMEM_N1>>>(xr,   nullptr, WqT, q, DD, DD, DD, DD, 0, 0, 0, nullptr, nullptr, q2);

    transpose_kernel<<<dim3(16, 16), dim3(32, 8)>>>(Wv, WvT, DD, DD);
    tc_gemm<0,0,1,2><<<dim3(SSEQ / 256, DD / 128, NB), 256, SMEM_N2>>>(
        WvT, nullptr, srcr, vT, SSEQ, DD, DD, DD,
        0, (long long)SSEQ * DD, (long long)DD * SSEQ, nullptr, nullptr, nullptr);

    transpose_kernel<<<dim3(16, 16), dim3(32, 8)>>>(Wm, WmT, DD, DD);
    transpose_kernel<<<dim3(32, 32), dim3(32, 8)>>>(W1, W1T, 2 * DD, 2 * DD);
    transpose_kernel<<<dim3(16, 32), dim3(32, 8)>>>(W2, W2T, 2 * DD, DD);
    cudaMemsetAsync(ssum, 0, NB * LQ * sizeof(float));

    // P_un = exp(dist - 12) fp16; row sums accumulated atomically (shift cancels)
    tc_gemm<1,0,1,2><<<dim3(SSEQ / 256, LQ / 128, NB), 256, SMEM_N2>>>(
        q, nullptr, k, sc, SSEQ, DD, DD, DD,
        (long long)LQ * DD, (long long)SSEQ * DD, (long long)LQ * SSEQ, q2, k2, ssum);

    // message = (P_un @ v) / rowsum  (fp16 out)  -- N=128 tiles: 256 CTAs
    tc_gemm<3,0,1,1><<<dim3(4, LQ / 128, NB), 256, SMEM_N1>>>(
        sc, nullptr, vT, msg, DD, SSEQ, SSEQ, SSEQ,
        (long long)LQ * SSEQ, (long long)DD * SSEQ, (long long)LQ * DD, ssum, nullptr, nullptr);

    // mw = message @ Wm (fp32 out); mln = LN(mw) fp16
    tc_gemm<0,0,0,1><<<dim3(4, 64, 1), 256, SMEM_N1>>>(msg, nullptr, WmT, mw, DD, DD, DD, DD, 0, 0, 0, nullptr, nullptr, nullptr);
    layernorm_kernel<1><<<NB * LQ, 128>>>(mw, g1, b1, nullptr, mln);

    // hid = relu([x, mln] @ W1) fp16  -- N=128 tiles: 512 CTAs
    tc_gemm<2,1,1,1><<<dim3(8, 64, 1), 256, SMEM_N1>>>(xr, mln, W1T, hid, 2 * DD, 2 * DD, DD, 2 * DD, 0, 0, 0, nullptr, nullptr, nullptr);

    // ffn = hid @ W2 (fp32 out)
    tc_gemm<0,0,0,1><<<dim3(4, 64, 1), 256, SMEM_N1>>>(hid, nullptr, W2T, ffn, DD, 2 * DD, 2 * DD, 2 * DD, 0, 0, 0, nullptr, nullptr, nullptr);

    // out = x + LN(ffn)   (residual uses ORIGINAL fp32 x)
    layernorm_kernel<0><<<NB * LQ, 128>>>(ffn, g2, b2, x, out);
}

// round 17
// speedup vs baseline: 1.1049x; 1.0046x over previous
#include <cuda_runtime.h>
#include <cuda_fp16.h>
#include <cstdint>

// Problem dims (fixed)
#define NB   8
#define LQ   1024
#define SSEQ 4096
#define DD   512

#ifndef __CUDA_ARCH_SPECIFIC__
#define __CUDA_ARCH_SPECIFIC__ 0
#endif
#if defined(__CUDA_ARCH_FEAT_SM103_ALL) || defined(__CUDA_ARCH_FEAT_SM100_ALL) || (__CUDA_ARCH_SPECIFIC__ >= 1000)
#define HAS_TCGEN05 1
#else
#define HAS_TCGEN05 0
#endif

// ---------------- static device scratch (no allocations allowed) ----------------
static __device__ __half g_q  [NB * LQ * DD];
static __device__ __half g_k  [NB * SSEQ * DD];
static __device__ __half g_vT [NB * DD * SSEQ];
static __device__ __half g_s  [NB * LQ * SSEQ];       // exp(dist-12), unnormalized
static __device__ __half g_msg[NB * LQ * DD];
static __device__ __half g_mln[NB * LQ * DD];
static __device__ __half g_hid[NB * LQ * 2 * DD];
static __device__ __half g_xr [NB * LQ * DD];
static __device__ __half g_srcr[NB * SSEQ * DD];
static __device__ __half g_wth[4 * DD * DD + 4 * DD * DD + 2 * DD * DD];
static __device__ float g_q2 [NB * LQ];
static __device__ float g_k2 [NB * SSEQ];
static __device__ float g_ssum[NB * LQ];
static __device__ float g_mw [NB * LQ * DD];
static __device__ float g_ffn[NB * LQ * DD];

// ======================= PTX helpers =======================
__device__ __forceinline__ uint32_t smem_u32(const void* p) {
    uint32_t a;
    asm("{ .reg .u64 t; cvta.to.shared.u64 t, %1; cvt.u32.u64 %0, t; }" : "=r"(a) : "l"(p));
    return a;
}
__device__ __forceinline__ uint32_t h2_bits(__half2 h) {
    return *reinterpret_cast<uint32_t*>(&h);
}
#define CP_ASYNC16(dst, src) \
    asm volatile("cp.async.cg.shared.global [%0], [%1], 16;" :: "r"(dst), "l"(src) : "memory")
#define CP_COMMIT() asm volatile("cp.async.commit_group;" ::: "memory")
#define CP_WAIT1()  asm volatile("cp.async.wait_group 1;" ::: "memory")
#define CP_WAIT0()  asm volatile("cp.async.wait_group 0;" ::: "memory")

#if HAS_TCGEN05
__device__ __forceinline__ uint32_t elect_one() {
    uint32_t pred;
    asm volatile("{\n\t.reg .pred p;\n\telect.sync _|p, 0xFFFFFFFF;\n\t"
                 "selp.b32 %0, 1, 0, p;\n\t}" : "=r"(pred));
    return pred;
}
#define MBAR_INIT(addr, cnt) \
    asm volatile("mbarrier.init.shared.b64 [%0], %1;" :: "r"(addr), "r"(cnt) : "memory")
#define MBAR_INVAL(addr) \
    asm volatile("mbarrier.inval.shared.b64 [%0];" :: "r"(addr) : "memory")
__device__ __forceinline__ void mbar_wait(uint32_t addr, uint32_t parity) {
    uint32_t done;
    asm volatile("{\n\t.reg .pred p;\n\t"
                 "mbarrier.try_wait.parity.acquire.cta.shared::cta.b64 p, [%1], %2;\n\t"
                 "selp.b32 %0, 1, 0, p;\n\t}" : "=r"(done) : "r"(addr), "r"(parity) : "memory");
    if (!done) {
        asm volatile("{\n\t.reg .pred P1;\n\t"
                     "W_%=:\n\t"
                     "mbarrier.try_wait.parity.acquire.cta.shared::cta.b64 P1, [%0], %1, 0x989680;\n\t"
                     "@P1 bra.uni D_%=;\n\t"
                     "bra.uni W_%=;\n\t"
                     "D_%=:\n\t}" :: "r"(addr), "r"(parity) : "memory");
    }
}
#define TC_ALLOC(smem_addr, n) \
    asm volatile("tcgen05.alloc.cta_group::1.sync.aligned.shared::cta.b32 [%0], %1;" \
                 :: "r"(smem_addr), "r"(n) : "memory")
#define TC_DEALLOC(tmem, n) \
    asm volatile("tcgen05.dealloc.cta_group::1.sync.aligned.b32 %0, %1;" :: "r"(tmem), "r"(n))
#define TC_RELINQ() \
    asm volatile("tcgen05.relinquish_alloc_permit.cta_group::1.sync.aligned;")
#define TC_COMMIT(mbar) \
    asm volatile("tcgen05.commit.cta_group::1.mbarrier::arrive::one.shared::cluster.b64 [%0];" \
                 :: "r"(mbar) : "memory")
#define TC_FENCE_AFTER() asm volatile("tcgen05.fence::after_thread_sync;" ::: "memory")
#define TC_WAIT_LD()     asm volatile("tcgen05.wait::ld.sync.aligned;" ::: "memory")
#define FENCE_ASYNC()    asm volatile("fence.proxy.async.shared::cta;" ::: "memory")

__device__ __forceinline__ void mma_f16_ss(uint32_t d, uint64_t a, uint64_t b,
                                           uint32_t idesc, uint32_t en) {
    asm volatile("{\n\t.reg .pred p;\n\tsetp.ne.u32 p, %4, 0;\n\t"
                 "tcgen05.mma.cta_group::1.kind::f16 [%0], %1, %2, %3, {%5,%5,%5,%5}, p;\n\t}"
                 :: "r"(d), "l"(a), "l"(b), "r"(idesc), "r"(en), "r"(0u) : "memory");
}
__device__ __forceinline__ void tmem_ld_x32(uint32_t* r, uint32_t addr) {
    asm volatile(
        "tcgen05.ld.sync.aligned.32x32b.x32.b32 "
        "{%0,%1,%2,%3,%4,%5,%6,%7,%8,%9,%10,%11,%12,%13,%14,%15,"
        "%16,%17,%18,%19,%20,%21,%22,%23,%24,%25,%26,%27,%28,%29,%30,%31}, [%32];"
        : "=r"(r[0]), "=r"(r[1]), "=r"(r[2]), "=r"(r[3]), "=r"(r[4]), "=r"(r[5]),
          "=r"(r[6]), "=r"(r[7]), "=r"(r[8]), "=r"(r[9]), "=r"(r[10]), "=r"(r[11]),
          "=r"(r[12]), "=r"(r[13]), "=r"(r[14]), "=r"(r[15]), "=r"(r[16]), "=r"(r[17]),
          "=r"(r[18]), "=r"(r[19]), "=r"(r[20]), "=r"(r[21]), "=r"(r[22]), "=r"(r[23]),
          "=r"(r[24]), "=r"(r[25]), "=r"(r[26]), "=r"(r[27]), "=r"(r[28]), "=r"(r[29]),
          "=r"(r[30]), "=r"(r[31])
        : "r"(addr));
}
__device__ __forceinline__ uint32_t sw128(uint32_t b) { return b ^ ((b >> 3) & 0x70); }
static __device__ __forceinline__ uint64_t make_desc(uint32_t addr) {
    const uint64_t base = (uint64_t(2) << 61) | (uint64_t(1) << 46)
                        | (uint64_t(64) << 32) | (uint64_t(1) << 16);
    return base | ((uint64_t)(addr >> 4) & 0x3FFF);
}
#define IDESC_F16 ((1u << 4) | ((128u / 8u) << 17) | ((128u / 16u) << 24))
#endif  // HAS_TCGEN05

// ======================================================================
// NT GEMM: C[M,N] = A[M,K] * Bt[N,K]^T; fp16 operands, fp32 accumulate.
// CTA tile 128(M) x (NH*128)(N), K chunks of 64. 2-slot ring
// (slot = A 16KB + NH x B 16KB), so NH=2 -> 2 CTAs/SM, NH=1 -> 3 CTAs/SM.
// R10-proven mainloop: cp.async + commit-group pipeline (depth 2), one
// __syncthreads per stage, mbarrier guarding slot reuse vs MMA completion.
// Epilogue: direct coalesced gmem stores (lane owns row x 32 consecutive cols).
// EPI: 0 none, 1 exp(dist-12)+row-sum, 2 relu, 3 div-by-rn, 4 fp16+sumsq.
// OUTH: 1 fp16 out, 0 fp32 out.  DUAL: A = [gA | gA2] along K.
// ======================================================================
template<int EPI, int DUAL, int OUTH, int NH>
__global__ __launch_bounds__(256)
void tc_gemm(const __half* __restrict__ gA, const __half* __restrict__ gA2,
             const __half* __restrict__ gB, void* __restrict__ gC,
             int N, int K, int lda, int ldb,
             long long sA, long long sB, long long sC,
             const float* __restrict__ rn, const float* __restrict__ cn,
             float* __restrict__ sum)
{
    extern __shared__ __align__(1024) char dyn_smem[];

    const int TILE_N = NH * 128;
    const int SLOT   = 16384 * (1 + NH);

    const int tid = threadIdx.x;
    const int wid = tid >> 5, lane = tid & 31;

    const long long z = blockIdx.z;
    const __half* Abase  = gA + z * sA + (long long)blockIdx.y * 128 * lda;
    const __half* A2base = DUAL ? (gA2 + (long long)blockIdx.y * 128 * lda) : nullptr;
    const __half* Bbase  = gB + z * sB + (long long)blockIdx.x * TILE_N * ldb;
    const long long Coff = z * sC + (long long)blockIdx.y * 128 * N + blockIdx.x * TILE_N;
    const int Mtot = gridDim.y * 128;

#if HAS_TCGEN05
    __shared__ uint32_t s_tmem[1];
    __shared__ __align__(8) uint64_t s_mbar[2];

    const uint32_t smem_base = smem_u32(dyn_smem);
    const uint32_t mbar_base = smem_u32(&s_mbar[0]);

    if (wid == 0) {
        TC_ALLOC(smem_u32(s_tmem), NH * 128);
        TC_RELINQ();
    }
    if (tid == 0) { MBAR_INIT(mbar_base, 1); MBAR_INIT(mbar_base + 8, 1); }
    __syncthreads();
    const uint32_t tmem = s_tmem[0];

    // loader geometry: rows of 64 halfs = 128B, SW128; 16B = 8 halfs
    const int r0 = tid >> 3, c0 = tid & 7;

    auto cp_stage = [&](int s) {
        const int slot = s & 1;
        const uint32_t sbase = smem_base + slot * SLOT;
        const int k0 = s * 64;
        const __half* Ap = DUAL ? (k0 < 512 ? Abase + k0 : A2base + (k0 - 512)) : (Abase + k0);
        const __half* Bp = Bbase + k0;
#pragma unroll
        for (int j = 0; j < 4; j++) {
            int row = r0 + j * 32;
            CP_ASYNC16(sbase + sw128((uint32_t)(row * 128 + c0 * 16)),
                       Ap + (long long)row * lda + c0 * 8);
        }
#pragma unroll
        for (int j = 0; j < 4 * NH; j++) {
            int row = r0 + j * 32;                 // 0..TILE_N-1
            int half = row >> 7;                   // which 128-row B block
            int rloc = row & 127;
            uint32_t off = (uint32_t)(16384 * (1 + half))
                         + sw128((uint32_t)(rloc * 128 + c0 * 16));
            CP_ASYNC16(sbase + off, Bp + (long long)row * ldb + c0 * 8);
        }
        CP_COMMIT();
    };

    const int nst = K / 64;                        // 8 / 16 / 64
    cp_stage(0);
    cp_stage(1);
    for (int s = 0; s < nst; s++) {
        const int slot = s & 1;
        if (s == nst - 1) CP_WAIT0(); else CP_WAIT1();
        __syncthreads();
        if (wid == 0) {
            FENCE_ASYNC();
            if (elect_one()) {
                uint32_t aAddr = smem_base + slot * SLOT;
                uint64_t ad = make_desc(aAddr);
#pragma unroll
                for (int st = 0; st < 4; st++) {
                    uint32_t en = (s > 0 || st > 0) ? 1u : 0u;
#pragma unroll
                    for (int h = 0; h < NH; h++) {
                        uint64_t bd = make_desc(aAddr + 16384 * (1 + h));
                        mma_f16_ss(tmem + h * 128, ad + st * 2, bd + st * 2, IDESC_F16, en);
                    }
                }
                TC_COMMIT(mbar_base + slot * 8);
            }
        }
        if (s + 2 < nst) {
            mbar_wait(mbar_base + slot * 8, (s >> 1) & 1);
            cp_stage(s + 2);
        }
    }
    {
        const int L = nst - 1;
        mbar_wait(mbar_base + (L & 1) * 8, (L >> 1) & 1);
    }
    TC_FENCE_AFTER();

    // ---------------- epilogue: direct gmem stores ----------------
    float rv = 0.0f, rinv = 0.0f, psum = 0.0f, cnv = 0.0f;
    if (wid < 4) {
        int rowg = (int)(z * Mtot) + blockIdx.y * 128 + wid * 32 + lane;
        if (EPI == 1) rv = rn[rowg];
        if (EPI == 3) rinv = 1.0f / rn[rowg];
    }

    if (wid < 4) {
        const int row = wid * 32 + lane;
#pragma unroll
        for (int ch = 0; ch < 4 * NH; ch++) {
            uint32_t r[32];
            tmem_ld_x32(r, tmem + ch * 32);
            TC_WAIT_LD();
            if (EPI == 1) cnv = cn[z * N + (long long)blockIdx.x * TILE_N + ch * 32 + lane];
            float v[32];
#pragma unroll
            for (int c = 0; c < 32; c++) {
                float t = __uint_as_float(r[c]);
                if (EPI == 1) {
                    float cc = __shfl_sync(0xffffffffu, cnv, c);
                    t = __expf(sqrtf(fmaxf(rv + cc - 2.0f * t, 0.0f)) - 12.0f);
                    t = __half2float(__float2half_rn(t));   // sum the STORED value
                    psum += t;
                } else if (EPI == 2) {
                    t = fmaxf(t, 0.0f);
                } else if (EPI == 3) {
                    t *= rinv;
                } else if (EPI == 4) {
                    t = __half2float(__float2half_rn(t));   // rownorm of STORED fp16
                    psum += t * t;
                }
                v[c] = t;
            }
            const long long base = Coff + (long long)row * N + ch * 32;
            if (OUTH) {
                __half* o = (__half*)gC + base;
#pragma unroll
                for (int c = 0; c < 32; c += 8) {
                    __half2 h0 = __floats2half2_rn(v[c + 0], v[c + 1]);
                    __half2 h1 = __floats2half2_rn(v[c + 2], v[c + 3]);
                    __half2 h2 = __floats2half2_rn(v[c + 4], v[c + 5]);
                    __half2 h3 = __floats2half2_rn(v[c + 6], v[c + 7]);
                    uint4 pack;
                    pack.x = h2_bits(h0); pack.y = h2_bits(h1);
                    pack.z = h2_bits(h2); pack.w = h2_bits(h3);
                    *(uint4*)(o + c) = pack;
                }
            } else {
                float* o = (float*)gC + base;
#pragma unroll
                for (int c = 0; c < 32; c += 4)
                    *(float4*)(o + c) = make_float4(v[c], v[c + 1], v[c + 2], v[c + 3]);
            }
        }
        if (EPI == 1 || EPI == 4) {
            int rowg = (int)(z * Mtot) + blockIdx.y * 128 + row;
            atomicAdd(&sum[rowg], psum);
        }
    }
    __syncthreads();

    if (tid == 0) { MBAR_INVAL(mbar_base); MBAR_INVAL(mbar_base + 8); }
    __syncthreads();
    if (wid == 0) TC_DEALLOC(tmem, NH * 128);

#else
    // ---- trivial scalar fallback (compute_103 pass only; never selected) ----
    const int TILE = 128 * TILE_N;
    for (int idx = tid; idx < TILE; idx += 256) {
        int row = idx / TILE_N, col = idx % TILE_N;
        float acc = 0.0f;
        for (int kk = 0; kk < K; kk++) {
            const __half* Ap = DUAL ? (kk < 512 ? Abase + kk : A2base + (kk - 512)) : (Abase + kk);
            float a = __half2float(Ap[(long long)row * lda]);
            float b = __half2float(Bbase[(long long)col * ldb + kk]);
            acc += a * b;
        }
        float v = acc;
        if (EPI == 1) {
            float rr = rn[z * Mtot + blockIdx.y * 128 + row];
            float cc = cn[z * N + blockIdx.x * TILE_N + col];
            v = __expf(sqrtf(fmaxf(rr + cc - 2.0f * v, 0.0f)) - 12.0f);
            v = __half2float(__float2half_rn(v));
            atomicAdd(&sum[z * Mtot + blockIdx.y * 128 + row], v);
        } else if (EPI == 2) v = fmaxf(v, 0.0f);
        else if (EPI == 3) v /= rn[z * Mtot + blockIdx.y * 128 + row];
        else if (EPI == 4) {
            v = __half2float(__float2half_rn(v));
            atomicAdd(&sum[z * Mtot + blockIdx.y * 128 + row], v * v);
        }
        long long o = Coff + (long long)row * N + col;
        if (OUTH) ((__half*)gC)[o] = __float2half_rn(v);
        else      ((float*)gC)[o] = v;
    }
#endif
}

// ---------------- reductions ----------------
__device__ __forceinline__ float warpReduceSum(float v) {
    v += __shfl_xor_sync(0xffffffffu, v, 16);
    v += __shfl_xor_sync(0xffffffffu, v, 8);
    v += __shfl_xor_sync(0xffffffffu, v, 4);
    v += __shfl_xor_sync(0xffffffffu, v, 2);
    v += __shfl_xor_sync(0xffffffffu, v, 1);
    return v;
}
__device__ __forceinline__ float blockAllReduceSum(float v, float* sh) {
    int lane = threadIdx.x & 31, wid = threadIdx.x >> 5;
    v = warpReduceSum(v);
    if (lane == 0) sh[wid] = v;
    __syncthreads();
    int nw = blockDim.x >> 5;
    float t = (lane < nw) ? sh[lane] : 0.0f;
    t = warpReduceSum(t);
    __syncthreads();
    return t;
}

// ---------------- fp32 -> fp16 convert ----------------
__global__ __launch_bounds__(256)
void convert_kernel(const float* __restrict__ in, __half* __restrict__ out, int n4)
{
    int i = blockIdx.x * 256 + threadIdx.x;
    if (i < n4) {
        float4 v = *(const float4*)(in + 4 * (long long)i);
        *(__half2*)(out + 4 * (long long)i)     = __floats2half2_rn(v.x, v.y);
        *(__half2*)(out + 4 * (long long)i + 2) = __floats2half2_rn(v.z, v.w);
    }
}

// ---------------- fp32 transpose -> fp16 ----------------
__global__ __launch_bounds__(256)
void transpose_kernel(const float* __restrict__ in, __half* __restrict__ out,
                      int R, int C)
{
    __shared__ float t[32][33];
    int bx = blockIdx.x * 32, by = blockIdx.y * 32;
    int x = bx + threadIdx.x;
#pragma unroll
    for (int j = 0; j < 32; j += 8)
        t[threadIdx.y + j][threadIdx.x] = in[(long long)(by + threadIdx.y + j) * C + x];
    __syncthreads();
    int x2 = by + threadIdx.x;
#pragma unroll
    for (int j = 0; j < 32; j += 8)
        out[(long long)(bx + threadIdx.y + j) * R + x2] = __float2half_rn(t[threadIdx.x][threadIdx.y + j]);
}

// ---------------- LayerNorm over D=512 (fp32 in; fp16 or fp32+res out) -----
template<int OUTH>
__global__ __launch_bounds__(128)
void layernorm_kernel(const float* __restrict__ X, const float* __restrict__ G,
                      const float* __restrict__ Bv, const float* __restrict__ R,
                      void* __restrict__ O)
{
    __shared__ float sh[32];
    long long row = blockIdx.x;
    int c = threadIdx.x * 4;
    float4 v = *(const float4*)(X + row * DD + c);

    float s = v.x + v.y + v.z + v.w;
    s = blockAllReduceSum(s, sh);
    float mu = s * (1.0f / DD);

    float d0 = v.x - mu, d1 = v.y - mu, d2 = v.z - mu, d3 = v.w - mu;
    float s2 = d0 * d0 + d1 * d1 + d2 * d2 + d3 * d3;
    s2 = blockAllReduceSum(s2, sh);
    float inv = rsqrtf(s2 * (1.0f / DD) + 1e-5f);

    float4 gg = *(const float4*)(G + c);
    float4 bb = *(const float4*)(Bv + c);
    float o0 = d0 * inv * gg.x + bb.x;
    float o1 = d1 * inv * gg.y + bb.y;
    float o2 = d2 * inv * gg.z + bb.z;
    float o3 = d3 * inv * gg.w + bb.w;
    if (R) {
        float4 rr = *(const float4*)(R + row * DD + c);
        o0 += rr.x; o1 += rr.y; o2 += rr.z; o3 += rr.w;
    }
    if (OUTH) {
        __half* Oh = (__half*)O + row * DD + c;
        *(__half2*)(Oh)     = __floats2half2_rn(o0, o1);
        *(__half2*)(Oh + 2) = __floats2half2_rn(o2, o3);
    } else {
        *(float4*)((float*)O + row * DD + c) = make_float4(o0, o1, o2, o3);
    }
}

// ======================================================================
#define SMEM_N2 98304   // 2 x 48KB ring (NH=2) -> 2 CTAs/SM
#define SMEM_N1 65536   // 2 x 32KB ring (NH=1) -> 3 CTAs/SM

extern "C" void kernel_launch(void* const* d_in, const int* in_sizes, int n_in,
                              void* d_out, int out_size)
{
    (void)in_sizes; (void)n_in; (void)out_size;
    const float* x   = (const float*)d_in[0];
    const float* src = (const float*)d_in[1];
    const float* Wq  = (const float*)d_in[2];
    const float* Wk  = (const float*)d_in[3];
    const float* Wv  = (const float*)d_in[4];
    const float* Wm  = (const float*)d_in[5];
    const float* W1  = (const float*)d_in[6];
    const float* W2  = (const float*)d_in[7];
    const float* g1  = (const float*)d_in[8];
    const float* b1  = (const float*)d_in[9];
    const float* g2  = (const float*)d_in[10];
    const float* b2  = (const float*)d_in[11];
    float* out = (float*)d_out;

    __half *q, *k, *vT, *sc, *msg, *mln, *hid, *xr, *srcr, *wth;
    float *q2, *k2, *ssum, *mw, *ffn;
    cudaGetSymbolAddress((void**)&q,    g_q);
    cudaGetSymbolAddress((void**)&k,    g_k);
    cudaGetSymbolAddress((void**)&vT,   g_vT);
    cudaGetSymbolAddress((void**)&sc,   g_s);
    cudaGetSymbolAddress((void**)&msg,  g_msg);
    cudaGetSymbolAddress((void**)&mln,  g_mln);
    cudaGetSymbolAddress((void**)&hid,  g_hid);
    cudaGetSymbolAddress((void**)&xr,   g_xr);
    cudaGetSymbolAddress((void**)&srcr, g_srcr);
    cudaGetSymbolAddress((void**)&wth,  g_wth);
    cudaGetSymbolAddress((void**)&q2,   g_q2);
    cudaGetSymbolAddress((void**)&k2,   g_k2);
    cudaGetSymbolAddress((void**)&ssum, g_ssum);
    cudaGetSymbolAddress((void**)&mw,   g_mw);
    cudaGetSymbolAddress((void**)&ffn,  g_ffn);

    __half* WqT = wth;
    __half* WkT = wth + DD * DD;
    __half* WvT = wth + 2 * DD * DD;
    __half* WmT = wth + 3 * DD * DD;
    __half* W1T = wth + 4 * DD * DD;
    __half* W2T = wth + 8 * DD * DD;

    cudaFuncSetAttribute(tc_gemm<4,0,1,2>, cudaFuncAttributeMaxDynamicSharedMemorySize, SMEM_N2);
    cudaFuncSetAttribute(tc_gemm<4,0,1,1>, cudaFuncAttributeMaxDynamicSharedMemorySize, SMEM_N1);
    cudaFuncSetAttribute(tc_gemm<0,0,1,2>, cudaFuncAttributeMaxDynamicSharedMemorySize, SMEM_N2);
    cudaFuncSetAttribute(tc_gemm<1,0,1,2>, cudaFuncAttributeMaxDynamicSharedMemorySize, SMEM_N2);
    cudaFuncSetAttribute(tc_gemm<3,0,1,1>, cudaFuncAttributeMaxDynamicSharedMemorySize, SMEM_N1);
    cudaFuncSetAttribute(tc_gemm<0,0,0,1>, cudaFuncAttributeMaxDynamicSharedMemorySize, SMEM_N1);
    cudaFuncSetAttribute(tc_gemm<2,1,1,1>, cudaFuncAttributeMaxDynamicSharedMemorySize, SMEM_N1);

    // Launch order arranged so ncu (-s 5 -c 1) captures the k-projection GEMM.
    transpose_kernel<<<dim3(16, 16), dim3(32, 8)>>>(Wq, WqT, DD, DD);        // 0
    transpose_kernel<<<dim3(16, 16), dim3(32, 8)>>>(Wk, WkT, DD, DD);        // 1
    convert_kernel<<<(NB * SSEQ * DD / 4 + 255) / 256, 256>>>(src, srcr, NB * SSEQ * DD / 4); // 2
    convert_kernel<<<(NB * LQ * DD / 4 + 255) / 256,   256>>>(x,   xr,   NB * LQ * DD / 4);   // 3
    cudaMemsetAsync(k2, 0, NB * SSEQ * sizeof(float));                       // 4
    // 5: k = srcr @ WkT  (fp16 out, fused rownorm into k2)
    tc_gemm<4,0,1,2><<<dim3(2, 256, 1), 256, SMEM_N2>>>(srcr, nullptr, WkT, k, DD, DD, DD, DD, 0, 0, 0, nullptr, nullptr, k2);

    cudaMemsetAsync(q2, 0, NB * LQ * sizeof(float));
    tc_gemm<4,0,1,1><<<dim3(4, 64, 1),  256, SMEM_N1>>>(xr,   nullptr, WqT, q, DD, DD, DD, DD, 0, 0, 0, nullptr, nullptr, q2);

    transpose_kernel<<<dim3(16, 16), dim3(32, 8)>>>(Wv, WvT, DD, DD);
    tc_gemm<0,0,1,2><<<dim3(SSEQ / 256, DD / 128, NB), 256, SMEM_N2>>>(
        WvT, nullptr, srcr, vT, SSEQ, DD, DD, DD,
        0, (long long)SSEQ * DD, (long long)DD * SSEQ, nullptr, nullptr, nullptr);

    transpose_kernel<<<dim3(16, 16), dim3(32, 8)>>>(Wm, WmT, DD, DD);
    transpose_kernel<<<dim3(32, 32), dim3(32, 8)>>>(W1, W1T, 2 * DD, 2 * DD);
    transpose_kernel<<<dim3(16, 32), dim3(32, 8)>>>(W2, W2T, 2 * DD, DD);
    cudaMemsetAsync(ssum, 0, NB * LQ * sizeof(float));

    // P_un = exp(dist - 12) fp16; row sums accumulated atomically (shift cancels)
    tc_gemm<1,0,1,2><<<dim3(SSEQ / 256, LQ / 128, NB), 256, SMEM_N2>>>(
        q, nullptr, k, sc, SSEQ, DD, DD, DD,
        (long long)LQ * DD, (long long)SSEQ * DD, (long long)LQ * SSEQ, q2, k2, ssum);

    // message = (P_un @ v) / rowsum  (fp16 out)  -- N=128 tiles: 256 CTAs
    tc_gemm<3,0,1,1><<<dim3(4, LQ / 128, NB), 256, SMEM_N1>>>(
        sc, nullptr, vT, msg, DD, SSEQ, SSEQ, SSEQ,
        (long long)LQ * SSEQ, (long long)DD * SSEQ, (long long)LQ * DD, ssum, nullptr, nullptr);

    // mw = message @ Wm (fp32 out); mln = LN(mw) fp16
    tc_gemm<0,0,0,1><<<dim3(4, 64, 1), 256, SMEM_N1>>>(msg, nullptr, WmT, mw, DD, DD, DD, DD, 0, 0, 0, nullptr, nullptr, nullptr);
    layernorm_kernel<1><<<NB * LQ, 128>>>(mw, g1, b1, nullptr, mln);

    // hid = relu([x, mln] @ W1) fp16  -- N=128 tiles: 512 CTAs
    tc_gemm<2,1,1,1><<<dim3(8, 64, 1), 256, SMEM_N1>>>(xr, mln, W1T, hid, 2 * DD, 2 * DD, DD, 2 * DD, 0, 0, 0, nullptr, nullptr, nullptr);

    // ffn = hid @ W2 (fp32 out)
    tc_gemm<0,0,0,1><<<dim3(4, 64, 1), 256, SMEM_N1>>>(hid, nullptr, W2T, ffn, DD, 2 * DD, 2 * DD, 2 * DD, 0, 0, 0, nullptr, nullptr, nullptr);

    // out = x + LN(ffn)   (residual uses ORIGINAL fp32 x)
    layernorm_kernel<0><<<NB * LQ, 128>>>(ffn, g2, b2, x, out);
}